// round 6
// baseline (speedup 1.0000x reference)
#include <cuda_runtime.h>
#include <cuda_bf16.h>
#include <cstdint>

// Problem constants
#define KK   27
#define RR   50000
#define CIN  64
#define COUT 64
#define NIN  150000
#define NOUT 150000

#define TILE    128
#define NTILES  ((RR + TILE - 1) / TILE)      // 391
#define NPAIRS  ((NTILES + 1) / 2)            // 196
#define PPB     4                             // tile-pairs per block
#define NBX     ((NPAIRS + PPB - 1) / PPB)    // 49

// SMEM layout (byte offsets): W(hi|lo) 16K, A buffers 4x16K, osm/ism 2K
#define OFF_WH  0u
#define OFF_WL  8192u
#define OFF_A   16384u       // AH(tt) = OFF_A + tt*32768 ; AL(tt) = +16384
#define OFF_OSM 81920u
#define OFF_ISM 82944u
#define SMEM_BYTES 83968

// ---- global scratch ----------------------------------------------------------
__device__ __align__(16) unsigned short g_xsplit[(size_t)NIN * 128];   // [hi64|lo64]
__device__ __align__(16) unsigned short g_wsplit[(size_t)KK * 8192];   // wh|wl swizzled

// ---- helpers -------------------------------------------------------------------
__device__ __forceinline__ uint32_t smem_u32(const void* p) {
    uint32_t a;
    asm("{ .reg .u64 t; cvta.to.shared.u64 t, %1; cvt.u32.u64 %0, t; }" : "=r"(a) : "l"(p));
    return a;
}
__device__ __forceinline__ void ldm4(uint32_t addr, uint32_t& r0, uint32_t& r1,
                                     uint32_t& r2, uint32_t& r3) {
    asm volatile("ldmatrix.sync.aligned.m8n8.x4.shared.b16 {%0,%1,%2,%3}, [%4];"
                 : "=r"(r0), "=r"(r1), "=r"(r2), "=r"(r3) : "r"(addr));
}
__device__ __forceinline__ void mma_bf16(float4& d,
                                         uint32_t a0, uint32_t a1, uint32_t a2, uint32_t a3,
                                         uint32_t b0, uint32_t b1) {
    asm volatile("mma.sync.aligned.m16n8k16.row.col.f32.bf16.bf16.f32 "
                 "{%0,%1,%2,%3}, {%4,%5,%6,%7}, {%8,%9}, {%0,%1,%2,%3};"
                 : "+f"(d.x), "+f"(d.y), "+f"(d.z), "+f"(d.w)
                 : "r"(a0), "r"(a1), "r"(a2), "r"(a3), "r"(b0), "r"(b1));
}
__device__ __forceinline__ void red4(float* p, float a, float b, float c, float d) {
    asm volatile("red.global.add.v4.f32 [%0], {%1, %2, %3, %4};"
                 :: "l"(p), "f"(a), "f"(b), "f"(c), "f"(d) : "memory");
}
__device__ __forceinline__ void split_bf16(float v, unsigned short& h, unsigned short& l) {
    __nv_bfloat16 bh = __float2bfloat16(v);
    float fh = __bfloat162float(bh);
    __nv_bfloat16 bl = __float2bfloat16(v - fh);
    h = *reinterpret_cast<unsigned short*>(&bh);
    l = *reinterpret_cast<unsigned short*>(&bl);
}

// ---- precompute: split x into hi/lo bf16 table ---------------------------------
__global__ void split_x_kernel(const float* __restrict__ x) {
    int t = blockIdx.x * blockDim.x + threadIdx.x;
    if (t >= NIN * 8) return;
    int row = t >> 3, c8 = t & 7;
    const float4* p = (const float4*)(x + (size_t)row * 64 + c8 * 8);
    float4 a = p[0], b = p[1];
    float v[8] = {a.x, a.y, a.z, a.w, b.x, b.y, b.z, b.w};
    unsigned short hi[8], lo[8];
    #pragma unroll
    for (int j = 0; j < 8; j++) split_bf16(v[j], hi[j], lo[j]);
    *(uint4*)(g_xsplit + (size_t)row * 128 + c8 * 8)      = *(uint4*)hi;
    *(uint4*)(g_xsplit + (size_t)row * 128 + 64 + c8 * 8) = *(uint4*)lo;
}

// ---- precompute: split W, permute cout rows, pre-swizzle SW128 ------------------
// Row permutation r = ((o>>1)&7)*8 + 2*(o>>4) + (o&1): each mma lane's d-frag
// covers 16 consecutive couts -> shuffle-free red.v4 epilogue.
__global__ void split_w_kernel(const float* __restrict__ w) {
    int t = blockIdx.x * blockDim.x + threadIdx.x;
    if (t >= KK * CIN * COUT) return;
    int k = t / 4096, rem = t - k * 4096;
    int c = rem >> 6, o = rem & 63;
    unsigned short h, l;
    split_bf16(w[t], h, l);
    int r = ((o >> 1) & 7) * 8 + 2 * (o >> 4) + (o & 1);
    uint32_t off = (uint32_t)r * 128 + (uint32_t)c * 2;
    uint32_t sw  = off ^ ((off >> 3) & 0x70);
    g_wsplit[(size_t)k * 8192 + (sw >> 1)]        = h;
    g_wsplit[(size_t)k * 8192 + 4096 + (sw >> 1)] = l;
}

// ---- out = bias broadcast --------------------------------------------------------
__global__ void init_out_kernel(float4* __restrict__ out4, const float4* __restrict__ bias4) {
    int i = blockIdx.x * blockDim.x + threadIdx.x;
    if (i < NOUT * (COUT / 4)) out4[i] = bias4[i & (COUT / 4 - 1)];
}

// ---- main: coalesced gather -> mma (2 tiles / B load) -> red.v4 scatter ----------
extern "C" __global__ void __launch_bounds__(256, 2)
sparse_mma_kernel(const int* __restrict__ in_idx,
                  const int* __restrict__ out_idx,
                  float*     __restrict__ out)
{
    extern __shared__ __align__(1024) char smem[];
    const uint32_t sbase = smem_u32(smem);
    const int tid  = threadIdx.x;
    const int lane = tid & 31;
    const int wrp  = tid >> 5;
    const int k    = blockIdx.y;
    int* osm = (int*)(smem + OFF_OSM);   // 256 entries (2 tiles)
    int* ism = (int*)(smem + OFF_ISM);

    // stage W (pre-split, pre-permuted, pre-swizzled): 16KB copy
    {
        const uint4* wg  = (const uint4*)(g_wsplit + (size_t)k * 8192);
        uint4*       wsm = (uint4*)(smem + OFF_WH);
        #pragma unroll
        for (int i = tid; i < 1024; i += 256) wsm[i] = wg[i];
    }

    // ldmatrix A addressing: row = 16*wrp + (lane&15)
    const int arow = 16 * wrp + (lane & 15);
    const uint32_t a_xor  = (uint32_t)((arow & 7) << 4);
    const uint32_t a_row_bytes = (uint32_t)arow * 128;
    const uint32_t a_kofs = (uint32_t)(((lane >> 4) & 1) * 16);

    // ldmatrix B addressing: x4 #p covers ngroups {2p, 2p+1}
    const uint32_t b_xor  = (uint32_t)((lane & 7) << 4);
    const uint32_t b_kofs = (uint32_t)(((lane >> 3) & 1) * 16);
    uint32_t b_rb[4];
    #pragma unroll
    for (int p = 0; p < 4; p++)
        b_rb[p] = (uint32_t)(((2 * p + (lane >> 4)) * 8 + (lane & 7)) * 128);

    // epilogue constants
    const int tq = lane & 3;
    const int m1 = 16 * wrp + (lane >> 2);

    // gather constants: 8 lanes cooperatively load one 128B half-row
    const int gchunk = tid & 7;          // 16B chunk within half-row

    for (int i = 0; i < PPB; i++) {
        int pair = blockIdx.x * PPB + i;
        int t0 = pair * 2;
        if (t0 >= NTILES) break;

        // ---- stage rule indices for both tiles (coalesced) ----
        {
            int tt = tid >> 7, rl = tid & 127;
            int rg = (t0 + tt) * TILE + rl;
            bool v = rg < RR;
            int rr = k * RR + rg;
            ism[tid] = v ? in_idx[rr] : -1;
            osm[tid] = v ? out_idx[rr] : -1;
        }
        __syncthreads();

        // ---- coalesced gather: 512 half-rows (2 tiles x 128 rules x hi/lo) ----
        // warp-inst covers 4 full 128B half-rows -> 4 L1 wavefronts
        #pragma unroll
        for (int it = 0; it < 16; it++) {
            int hid  = it * 32 + (tid >> 3);   // 0..511
            int tt   = hid >> 8;
            int rl   = (hid >> 1) & 127;
            int half = hid & 1;
            int gi   = ism[hid >> 1];          // broadcast across 8 lanes
            if (gi >= 0) {
                uint4 v = *((const uint4*)(g_xsplit + (size_t)gi * 128 + half * 64) + gchunk);
                uint32_t off = (uint32_t)rl * 128 + gchunk * 16;
                uint32_t sw  = off ^ ((off >> 3) & 0x70);
                *(uint4*)(smem + OFF_A + (uint32_t)tt * 32768u
                               + (uint32_t)half * 16384u + sw) = v;
            }
        }
        __syncthreads();

        // ---- MMA: per kstep load B once, apply to both tiles ----
        float4 acc[2][8];
        #pragma unroll
        for (int tt = 0; tt < 2; tt++)
            #pragma unroll
            for (int g = 0; g < 8; g++) acc[tt][g] = make_float4(0.f, 0.f, 0.f, 0.f);

        uint32_t Ah[2][4];   // kept across bh->bl phases

        #pragma unroll
        for (int ks = 0; ks < 4; ks++) {
            uint32_t cola = (uint32_t)(32 * ks) + a_kofs;
            uint32_t colb = (uint32_t)(32 * ks) + b_kofs;

            uint32_t B[16];
            #pragma unroll
            for (int p = 0; p < 4; p++)
                ldm4(sbase + OFF_WH + b_rb[p] + (colb ^ b_xor),
                     B[4 * p], B[4 * p + 1], B[4 * p + 2], B[4 * p + 3]);

            #pragma unroll
            for (int tt = 0; tt < 2; tt++) {
                uint32_t ahb = sbase + OFF_A + (uint32_t)tt * 32768u + a_row_bytes;
                ldm4(ahb + (cola ^ a_xor), Ah[tt][0], Ah[tt][1], Ah[tt][2], Ah[tt][3]);
                uint32_t al0, al1, al2, al3;
                ldm4(ahb + 16384u + (cola ^ a_xor), al0, al1, al2, al3);
                #pragma unroll
                for (int g = 0; g < 8; g++)
                    mma_bf16(acc[tt][g], Ah[tt][0], Ah[tt][1], Ah[tt][2], Ah[tt][3],
                             B[2 * g], B[2 * g + 1]);
                #pragma unroll
                for (int g = 0; g < 8; g++)
                    mma_bf16(acc[tt][g], al0, al1, al2, al3, B[2 * g], B[2 * g + 1]);
            }

            #pragma unroll
            for (int p = 0; p < 4; p++)
                ldm4(sbase + OFF_WL + b_rb[p] + (colb ^ b_xor),
                     B[4 * p], B[4 * p + 1], B[4 * p + 2], B[4 * p + 3]);

            #pragma unroll
            for (int tt = 0; tt < 2; tt++)
                #pragma unroll
                for (int g = 0; g < 8; g++)
                    mma_bf16(acc[tt][g], Ah[tt][0], Ah[tt][1], Ah[tt][2], Ah[tt][3],
                             B[2 * g], B[2 * g + 1]);
        }
        __syncthreads();   // smem reads done before next pair's STS

        // ---- scatter: 16 consecutive couts per lane per row ----
        #pragma unroll
        for (int tt = 0; tt < 2; tt++) {
            int o1 = osm[tt * 128 + m1];
            int o2 = osm[tt * 128 + m1 + 8];
            if (o1 >= 0) {
                float* b = out + (size_t)o1 * COUT + 16 * tq;
                #pragma unroll
                for (int q = 0; q < 4; q++)
                    red4(b + 4 * q, acc[tt][2 * q].x, acc[tt][2 * q].y,
                                    acc[tt][2 * q + 1].x, acc[tt][2 * q + 1].y);
            }
            if (o2 >= 0) {
                float* b = out + (size_t)o2 * COUT + 16 * tq;
                #pragma unroll
                for (int q = 0; q < 4; q++)
                    red4(b + 4 * q, acc[tt][2 * q].z, acc[tt][2 * q].w,
                                    acc[tt][2 * q + 1].z, acc[tt][2 * q + 1].w);
            }
        }
    }
}

extern "C" void kernel_launch(void* const* d_in, const int* in_sizes, int n_in,
                              void* d_out, int out_size)
{
    const float* x       = (const float*)d_in[0];
    const float* w       = (const float*)d_in[1];
    const float* bias    = (const float*)d_in[2];
    const int*   in_idx  = (const int*)d_in[3];
    const int*   out_idx = (const int*)d_in[4];
    float*       out     = (float*)d_out;

    split_x_kernel<<<(NIN * 8 + 255) / 256, 256>>>(x);
    split_w_kernel<<<(KK * CIN * COUT + 255) / 256, 256>>>(w);

    {
        int n4 = NOUT * (COUT / 4);
        init_out_kernel<<<(n4 + 255) / 256, 256>>>((float4*)out, (const float4*)bias);
    }

    cudaFuncSetAttribute(sparse_mma_kernel,
                         cudaFuncAttributeMaxDynamicSharedMemorySize, SMEM_BYTES);
    dim3 grid(NBX, KK);
    sparse_mma_kernel<<<grid, 256, SMEM_BYTES>>>(in_idx, out_idx, out);
}

// round 7
// speedup vs baseline: 1.0960x; 1.0960x over previous
#include <cuda_runtime.h>
#include <cuda_bf16.h>
#include <cstdint>

// Problem constants
#define KK   27
#define RR   50000
#define CIN  64
#define COUT 64
#define NIN  150000
#define NOUT 150000

#define TILE    128
#define NTILES  ((RR + TILE - 1) / TILE)      // 391
#define NPAIRS  ((NTILES + 1) / 2)            // 196
#define PPB     4                             // tile-pairs per block
#define NBX     ((NPAIRS + PPB - 1) / PPB)    // 49

// SMEM layout: W(hi|lo) 16K, then 2 stages x 64K (stage = 2 tiles x (AH 16K | AL 16K))
#define OFF_WH  0u
#define OFF_WL  8192u
#define OFF_A   16384u
#define SMEM_BYTES 147456u   // 16K + 2*64K

// ---- global scratch ----------------------------------------------------------
__device__ __align__(16) unsigned short g_xsplit[(size_t)NIN * 128];   // [hi64|lo64]
__device__ __align__(16) unsigned short g_wsplit[(size_t)KK * 8192];   // wh|wl swizzled

// ---- helpers -------------------------------------------------------------------
__device__ __forceinline__ uint32_t smem_u32(const void* p) {
    uint32_t a;
    asm("{ .reg .u64 t; cvta.to.shared.u64 t, %1; cvt.u32.u64 %0, t; }" : "=r"(a) : "l"(p));
    return a;
}
__device__ __forceinline__ void ldm4(uint32_t addr, uint32_t& r0, uint32_t& r1,
                                     uint32_t& r2, uint32_t& r3) {
    asm volatile("ldmatrix.sync.aligned.m8n8.x4.shared.b16 {%0,%1,%2,%3}, [%4];"
                 : "=r"(r0), "=r"(r1), "=r"(r2), "=r"(r3) : "r"(addr));
}
__device__ __forceinline__ void mma_bf16(float4& d,
                                         uint32_t a0, uint32_t a1, uint32_t a2, uint32_t a3,
                                         uint32_t b0, uint32_t b1) {
    asm volatile("mma.sync.aligned.m16n8k16.row.col.f32.bf16.bf16.f32 "
                 "{%0,%1,%2,%3}, {%4,%5,%6,%7}, {%8,%9}, {%0,%1,%2,%3};"
                 : "+f"(d.x), "+f"(d.y), "+f"(d.z), "+f"(d.w)
                 : "r"(a0), "r"(a1), "r"(a2), "r"(a3), "r"(b0), "r"(b1));
}
__device__ __forceinline__ void red4(float* p, float a, float b, float c, float d) {
    asm volatile("red.global.add.v4.f32 [%0], {%1, %2, %3, %4};"
                 :: "l"(p), "f"(a), "f"(b), "f"(c), "f"(d) : "memory");
}
__device__ __forceinline__ void split_bf16(float v, unsigned short& h, unsigned short& l) {
    __nv_bfloat16 bh = __float2bfloat16(v);
    float fh = __bfloat162float(bh);
    __nv_bfloat16 bl = __float2bfloat16(v - fh);
    h = *reinterpret_cast<unsigned short*>(&bh);
    l = *reinterpret_cast<unsigned short*>(&bl);
}

// ---- precompute: split x into hi/lo bf16 table ---------------------------------
__global__ void split_x_kernel(const float* __restrict__ x) {
    int t = blockIdx.x * blockDim.x + threadIdx.x;
    if (t >= NIN * 8) return;
    int row = t >> 3, c8 = t & 7;
    const float4* p = (const float4*)(x + (size_t)row * 64 + c8 * 8);
    float4 a = p[0], b = p[1];
    float v[8] = {a.x, a.y, a.z, a.w, b.x, b.y, b.z, b.w};
    unsigned short hi[8], lo[8];
    #pragma unroll
    for (int j = 0; j < 8; j++) split_bf16(v[j], hi[j], lo[j]);
    *(uint4*)(g_xsplit + (size_t)row * 128 + c8 * 8)      = *(uint4*)hi;
    *(uint4*)(g_xsplit + (size_t)row * 128 + 64 + c8 * 8) = *(uint4*)lo;
}

// ---- precompute: split W, permute cout rows, pre-swizzle SW128 ------------------
__global__ void split_w_kernel(const float* __restrict__ w) {
    int t = blockIdx.x * blockDim.x + threadIdx.x;
    if (t >= KK * CIN * COUT) return;
    int k = t / 4096, rem = t - k * 4096;
    int c = rem >> 6, o = rem & 63;
    unsigned short h, l;
    split_bf16(w[t], h, l);
    int r = ((o >> 1) & 7) * 8 + 2 * (o >> 4) + (o & 1);
    uint32_t off = (uint32_t)r * 128 + (uint32_t)c * 2;
    uint32_t sw  = off ^ ((off >> 3) & 0x70);
    g_wsplit[(size_t)k * 8192 + (sw >> 1)]        = h;
    g_wsplit[(size_t)k * 8192 + 4096 + (sw >> 1)] = l;
}

// ---- out = bias broadcast --------------------------------------------------------
__global__ void init_out_kernel(float4* __restrict__ out4, const float4* __restrict__ bias4) {
    int i = blockIdx.x * blockDim.x + threadIdx.x;
    if (i < NOUT * (COUT / 4)) out4[i] = bias4[i & (COUT / 4 - 1)];
}

// ---- async gather of one tile-pair into stage s ----------------------------------
__device__ __forceinline__ void gather_pair_async(uint32_t sbase, int s, int t0, int k,
                                                  const int* __restrict__ in_idx, int tid)
{
    const int gchunk = tid & 7;     // 16B chunk within 128B half-row
    const int gid    = tid >> 3;    // half-row group id (0..31 per iter)
    #pragma unroll
    for (int it = 0; it < 16; it++) {
        int hid  = it * 32 + gid;          // 0..511
        int tt   = hid >> 8;
        int rl   = (hid >> 1) & 127;
        int half = hid & 1;
        int rg   = (t0 + tt) * TILE + rl;
        if (rg < RR) {
            int gi = __ldg(&in_idx[k * RR + rg]);   // broadcast across 8 lanes
            const void* src = (const char*)(g_xsplit + (size_t)gi * 128 + half * 64)
                            + gchunk * 16;
            uint32_t off = (uint32_t)rl * 128 + gchunk * 16;
            uint32_t sw  = off ^ ((off >> 3) & 0x70);
            uint32_t dst = sbase + OFF_A + ((uint32_t)s << 16)
                         + (uint32_t)tt * 32768u + (uint32_t)half * 16384u + sw;
            asm volatile("cp.async.cg.shared.global [%0], [%1], 16;"
                         :: "r"(dst), "l"(src) : "memory");
        }
    }
    asm volatile("cp.async.commit_group;" ::: "memory");
}

// ---- main: pipelined cp.async gather -> pair MMA -> red.v4 scatter ---------------
extern "C" __global__ void __launch_bounds__(256, 2)
sparse_mma_kernel(const int* __restrict__ in_idx,
                  const int* __restrict__ out_idx,
                  float*     __restrict__ out)
{
    extern __shared__ __align__(1024) char smem[];
    const uint32_t sbase = smem_u32(smem);
    const int tid  = threadIdx.x;
    const int lane = tid & 31;
    const int wrp  = tid >> 5;
    const int k    = blockIdx.y;

    // prologue: issue gather for first pair, then stage W while it flies
    const int pair0 = blockIdx.x * PPB;
    gather_pair_async(sbase, 0, pair0 * 2, k, in_idx, tid);

    {
        const uint4* wg  = (const uint4*)(g_wsplit + (size_t)k * 8192);
        uint4*       wsm = (uint4*)(smem + OFF_WH);
        #pragma unroll
        for (int i = tid; i < 1024; i += 256) wsm[i] = wg[i];
    }

    // ldmatrix A addressing: row = 16*wrp + (lane&15)
    const int arow = 16 * wrp + (lane & 15);
    const uint32_t a_xor  = (uint32_t)((arow & 7) << 4);
    const uint32_t a_row_bytes = (uint32_t)arow * 128;
    const uint32_t a_kofs = (uint32_t)(((lane >> 4) & 1) * 16);

    // ldmatrix B addressing
    const uint32_t b_xor  = (uint32_t)((lane & 7) << 4);
    const uint32_t b_kofs = (uint32_t)(((lane >> 3) & 1) * 16);
    uint32_t b_rb[4];
    #pragma unroll
    for (int p = 0; p < 4; p++)
        b_rb[p] = (uint32_t)(((2 * p + (lane >> 4)) * 8 + (lane & 7)) * 128);

    // epilogue constants
    const int tq = lane & 3;
    const int m1 = 16 * wrp + (lane >> 2);

    int s = 0;
    #pragma unroll 1
    for (int i = 0; i < PPB; i++) {
        int t0 = (pair0 + i) * 2;

        // issue next pair's gather into the other stage, then wait for current
        if (i + 1 < PPB) {
            gather_pair_async(sbase, s ^ 1, t0 + 2, k, in_idx, tid);
            asm volatile("cp.async.wait_group 1;" ::: "memory");
        } else {
            asm volatile("cp.async.wait_group 0;" ::: "memory");
        }
        __syncthreads();

        // ---- MMA on stage s: per kstep load B once, apply to both tiles ----
        float4 acc[2][8];
        #pragma unroll
        for (int tt = 0; tt < 2; tt++)
            #pragma unroll
            for (int g = 0; g < 8; g++) acc[tt][g] = make_float4(0.f, 0.f, 0.f, 0.f);

        const uint32_t stage = sbase + OFF_A + ((uint32_t)s << 16);
        uint32_t Ah[2][4];

        #pragma unroll
        for (int ks = 0; ks < 4; ks++) {
            uint32_t cola = (uint32_t)(32 * ks) + a_kofs;
            uint32_t colb = (uint32_t)(32 * ks) + b_kofs;

            uint32_t B[16];
            #pragma unroll
            for (int p = 0; p < 4; p++)
                ldm4(sbase + OFF_WH + b_rb[p] + (colb ^ b_xor),
                     B[4 * p], B[4 * p + 1], B[4 * p + 2], B[4 * p + 3]);

            #pragma unroll
            for (int tt = 0; tt < 2; tt++) {
                uint32_t ahb = stage + (uint32_t)tt * 32768u + a_row_bytes;
                ldm4(ahb + (cola ^ a_xor), Ah[tt][0], Ah[tt][1], Ah[tt][2], Ah[tt][3]);
                uint32_t al0, al1, al2, al3;
                ldm4(ahb + 16384u + (cola ^ a_xor), al0, al1, al2, al3);
                #pragma unroll
                for (int g = 0; g < 8; g++)
                    mma_bf16(acc[tt][g], Ah[tt][0], Ah[tt][1], Ah[tt][2], Ah[tt][3],
                             B[2 * g], B[2 * g + 1]);
                #pragma unroll
                for (int g = 0; g < 8; g++)
                    mma_bf16(acc[tt][g], al0, al1, al2, al3, B[2 * g], B[2 * g + 1]);
            }

            #pragma unroll
            for (int p = 0; p < 4; p++)
                ldm4(sbase + OFF_WL + b_rb[p] + (colb ^ b_xor),
                     B[4 * p], B[4 * p + 1], B[4 * p + 2], B[4 * p + 3]);

            #pragma unroll
            for (int tt = 0; tt < 2; tt++)
                #pragma unroll
                for (int g = 0; g < 8; g++)
                    mma_bf16(acc[tt][g], Ah[tt][0], Ah[tt][1], Ah[tt][2], Ah[tt][3],
                             B[2 * g], B[2 * g + 1]);
        }
        __syncthreads();   // stage-s reads done before it is refilled at i+2

        // ---- scatter: 16 consecutive couts per lane per row ----
        #pragma unroll
        for (int tt = 0; tt < 2; tt++) {
            int rg1 = (t0 + tt) * TILE + m1;
            int rg2 = rg1 + 8;
            int o1 = (rg1 < RR) ? __ldg(&out_idx[k * RR + rg1]) : -1;
            int o2 = (rg2 < RR) ? __ldg(&out_idx[k * RR + rg2]) : -1;
            if (o1 >= 0) {
                float* b = out + (size_t)o1 * COUT + 16 * tq;
                #pragma unroll
                for (int q = 0; q < 4; q++)
                    red4(b + 4 * q, acc[tt][2 * q].x, acc[tt][2 * q].y,
                                    acc[tt][2 * q + 1].x, acc[tt][2 * q + 1].y);
            }
            if (o2 >= 0) {
                float* b = out + (size_t)o2 * COUT + 16 * tq;
                #pragma unroll
                for (int q = 0; q < 4; q++)
                    red4(b + 4 * q, acc[tt][2 * q].z, acc[tt][2 * q].w,
                                    acc[tt][2 * q + 1].z, acc[tt][2 * q + 1].w);
            }
        }
        s ^= 1;
    }
}

extern "C" void kernel_launch(void* const* d_in, const int* in_sizes, int n_in,
                              void* d_out, int out_size)
{
    const float* x       = (const float*)d_in[0];
    const float* w       = (const float*)d_in[1];
    const float* bias    = (const float*)d_in[2];
    const int*   in_idx  = (const int*)d_in[3];
    const int*   out_idx = (const int*)d_in[4];
    float*       out     = (float*)d_out;

    split_x_kernel<<<(NIN * 8 + 255) / 256, 256>>>(x);
    split_w_kernel<<<(KK * CIN * COUT + 255) / 256, 256>>>(w);

    {
        int n4 = NOUT * (COUT / 4);
        init_out_kernel<<<(n4 + 255) / 256, 256>>>((float4*)out, (const float4*)bias);
    }

    cudaFuncSetAttribute(sparse_mma_kernel,
                         cudaFuncAttributeMaxDynamicSharedMemorySize, SMEM_BYTES);
    dim3 grid(NBX, KK);
    sparse_mma_kernel<<<grid, 256, SMEM_BYTES>>>(in_idx, out_idx, out);
}

// round 8
// speedup vs baseline: 1.1984x; 1.0934x over previous
#include <cuda_runtime.h>
#include <cuda_bf16.h>
#include <cstdint>

// Problem constants
#define KK   27
#define RR   50000
#define CIN  64
#define COUT 64
#define NIN  150000
#define NOUT 150000

#define TILE    128
#define NTILES  ((RR + TILE - 1) / TILE)      // 391
#define NPAIRS  ((NTILES + 1) / 2)            // 196
#define PPB     4                             // tile-pairs per block
#define NBX     ((NPAIRS + PPB - 1) / PPB)    // 49
#define THREADS 512

// SMEM: W(hi|lo) 16K, then 2 stages x 64K (stage = 2 tiles x (AH 16K | AL 16K))
#define OFF_WH  0u
#define OFF_WL  8192u
#define OFF_A   16384u
#define SMEM_BYTES 147456u

// ---- global scratch ----------------------------------------------------------
__device__ __align__(16) unsigned short g_xsplit[(size_t)NIN * 128];   // [hi64|lo64]
__device__ __align__(16) unsigned short g_wsplit[(size_t)KK * 8192];   // wh|wl swizzled

// ---- helpers -------------------------------------------------------------------
__device__ __forceinline__ uint32_t smem_u32(const void* p) {
    uint32_t a;
    asm("{ .reg .u64 t; cvta.to.shared.u64 t, %1; cvt.u32.u64 %0, t; }" : "=r"(a) : "l"(p));
    return a;
}
__device__ __forceinline__ void ldm4(uint32_t addr, uint32_t& r0, uint32_t& r1,
                                     uint32_t& r2, uint32_t& r3) {
    asm volatile("ldmatrix.sync.aligned.m8n8.x4.shared.b16 {%0,%1,%2,%3}, [%4];"
                 : "=r"(r0), "=r"(r1), "=r"(r2), "=r"(r3) : "r"(addr));
}
__device__ __forceinline__ void mma_bf16(float4& d,
                                         uint32_t a0, uint32_t a1, uint32_t a2, uint32_t a3,
                                         uint32_t b0, uint32_t b1) {
    asm volatile("mma.sync.aligned.m16n8k16.row.col.f32.bf16.bf16.f32 "
                 "{%0,%1,%2,%3}, {%4,%5,%6,%7}, {%8,%9}, {%0,%1,%2,%3};"
                 : "+f"(d.x), "+f"(d.y), "+f"(d.z), "+f"(d.w)
                 : "r"(a0), "r"(a1), "r"(a2), "r"(a3), "r"(b0), "r"(b1));
}
__device__ __forceinline__ void red4(float* p, float a, float b, float c, float d) {
    asm volatile("red.global.add.v4.f32 [%0], {%1, %2, %3, %4};"
                 :: "l"(p), "f"(a), "f"(b), "f"(c), "f"(d) : "memory");
}
__device__ __forceinline__ void split_bf16(float v, unsigned short& h, unsigned short& l) {
    __nv_bfloat16 bh = __float2bfloat16(v);
    float fh = __bfloat162float(bh);
    __nv_bfloat16 bl = __float2bfloat16(v - fh);
    h = *reinterpret_cast<unsigned short*>(&bh);
    l = *reinterpret_cast<unsigned short*>(&bl);
}

// ---- precompute: split x into hi/lo bf16 table ---------------------------------
__global__ void split_x_kernel(const float* __restrict__ x) {
    int t = blockIdx.x * blockDim.x + threadIdx.x;
    if (t >= NIN * 8) return;
    int row = t >> 3, c8 = t & 7;
    const float4* p = (const float4*)(x + (size_t)row * 64 + c8 * 8);
    float4 a = p[0], b = p[1];
    float v[8] = {a.x, a.y, a.z, a.w, b.x, b.y, b.z, b.w};
    unsigned short hi[8], lo[8];
    #pragma unroll
    for (int j = 0; j < 8; j++) split_bf16(v[j], hi[j], lo[j]);
    *(uint4*)(g_xsplit + (size_t)row * 128 + c8 * 8)      = *(uint4*)hi;
    *(uint4*)(g_xsplit + (size_t)row * 128 + 64 + c8 * 8) = *(uint4*)lo;
}

// ---- precompute: split W, permute cout rows, pre-swizzle SW128 ------------------
// Perm r = ((o>>1)&7)*8 + 2*(o>>4) + (o&1): lane's d-frags cover consecutive couts.
__global__ void split_w_kernel(const float* __restrict__ w) {
    int t = blockIdx.x * blockDim.x + threadIdx.x;
    if (t >= KK * CIN * COUT) return;
    int k = t / 4096, rem = t - k * 4096;
    int c = rem >> 6, o = rem & 63;
    unsigned short h, l;
    split_bf16(w[t], h, l);
    int r = ((o >> 1) & 7) * 8 + 2 * (o >> 4) + (o & 1);
    uint32_t off = (uint32_t)r * 128 + (uint32_t)c * 2;
    uint32_t sw  = off ^ ((off >> 3) & 0x70);
    g_wsplit[(size_t)k * 8192 + (sw >> 1)]        = h;
    g_wsplit[(size_t)k * 8192 + 4096 + (sw >> 1)] = l;
}

// ---- out = bias broadcast --------------------------------------------------------
__global__ void init_out_kernel(float4* __restrict__ out4, const float4* __restrict__ bias4) {
    int i = blockIdx.x * blockDim.x + threadIdx.x;
    if (i < NOUT * (COUT / 4)) out4[i] = bias4[i & (COUT / 4 - 1)];
}

// ---- async gather of one tile-pair into stage s (512 threads) --------------------
__device__ __forceinline__ void gather_pair_async(uint32_t sbase, int s, int t0, int k,
                                                  const int* __restrict__ in_idx, int tid)
{
    const int gchunk = tid & 7;     // 16B chunk within 128B half-row
    const int gid    = tid >> 3;    // 0..63
    #pragma unroll
    for (int it = 0; it < 8; it++) {
        int hid  = it * 64 + gid;          // 0..511
        int tt   = hid >> 8;
        int rl   = (hid >> 1) & 127;
        int half = hid & 1;
        int rg   = (t0 + tt) * TILE + rl;
        if (rg < RR) {
            int gi = __ldg(&in_idx[k * RR + rg]);   // broadcast across 8 lanes
            const void* src = (const char*)(g_xsplit + (size_t)gi * 128 + half * 64)
                            + gchunk * 16;
            uint32_t off = (uint32_t)rl * 128 + gchunk * 16;
            uint32_t sw  = off ^ ((off >> 3) & 0x70);
            uint32_t dst = sbase + OFF_A + ((uint32_t)s << 16)
                         + (uint32_t)tt * 32768u + (uint32_t)half * 16384u + sw;
            asm volatile("cp.async.cg.shared.global [%0], [%1], 16;"
                         :: "r"(dst), "l"(src) : "memory");
        }
    }
    asm volatile("cp.async.commit_group;" ::: "memory");
}

// ---- main: 512-thr pipelined gather -> warp(rule-slice x n-half) MMA -> red.v4 ----
extern "C" __global__ void __launch_bounds__(THREADS, 1)
sparse_mma_kernel(const int* __restrict__ in_idx,
                  const int* __restrict__ out_idx,
                  float*     __restrict__ out)
{
    extern __shared__ __align__(1024) char smem[];
    const uint32_t sbase = smem_u32(smem);
    const int tid  = threadIdx.x;
    const int lane = tid & 31;
    const int wrp  = tid >> 5;          // 0..15
    const int k    = blockIdx.y;

    // prologue: issue first pair's gather, then stage W while it flies
    const int pair0 = blockIdx.x * PPB;
    gather_pair_async(sbase, 0, pair0 * 2, k, in_idx, tid);
    {
        const uint4* wg  = (const uint4*)(g_wsplit + (size_t)k * 8192);
        uint4*       wsm = (uint4*)(smem + OFF_WH);
        #pragma unroll
        for (int i = tid; i < 1024; i += THREADS) wsm[i] = wg[i];
    }

    // warp roles: n-half h, rule-slice s8 (32 rules = 2 m16 blocks in tile tts)
    const int h   = wrp & 1;
    const int s8  = wrp >> 1;           // 0..7
    const int tts = s8 >> 2;            // tile of this slice
    const int mrow0 = (s8 & 3) * 32 + (lane & 15);   // row in tile of mb=0 ldm

    // A ldmatrix addressing (per mb: +16 rows = +2048B)
    const uint32_t a_xor0 = (uint32_t)((mrow0 & 7) << 4);
    const uint32_t a_rb   = (uint32_t)tts * 32768u + (uint32_t)mrow0 * 128u;
    const uint32_t a_kofs = (uint32_t)(((lane >> 4) & 1) * 16);

    // B ldmatrix addressing: p in {2h, 2h+1} covers ngroups 4h..4h+3
    const uint32_t b_xor  = (uint32_t)((lane & 7) << 4);
    const uint32_t b_kofs = (uint32_t)(((lane >> 3) & 1) * 16);
    uint32_t b_rb[2];
    #pragma unroll
    for (int pp = 0; pp < 2; pp++) {
        int p = 2 * h + pp;
        b_rb[pp] = (uint32_t)(((2 * p + (lane >> 4)) * 8 + (lane & 7)) * 128);
    }

    // epilogue constants: lane covers couts [16tq+8h, +8) for 4 rule-rows
    const int tq = lane & 3;
    const int rrow = 32 * s8 + (lane >> 2);   // row within pair for mb=0, j=0

    int s = 0;
    #pragma unroll 1
    for (int i = 0; i < PPB; i++) {
        int t0 = (pair0 + i) * 2;

        if (i + 1 < PPB) {
            gather_pair_async(sbase, s ^ 1, t0 + 2, k, in_idx, tid);
            asm volatile("cp.async.wait_group 1;" ::: "memory");
        } else {
            asm volatile("cp.async.wait_group 0;" ::: "memory");
        }
        __syncthreads();

        // ---- MMA on stage s ----
        float4 acc[2][4];                 // [mb][ngroup-local]
        #pragma unroll
        for (int mb = 0; mb < 2; mb++)
            #pragma unroll
            for (int g = 0; g < 4; g++) acc[mb][g] = make_float4(0.f, 0.f, 0.f, 0.f);

        const uint32_t stage = sbase + OFF_A + ((uint32_t)s << 16);
        uint32_t Ah[2][4];

        #pragma unroll
        for (int ks = 0; ks < 4; ks++) {
            uint32_t cola = (uint32_t)(32 * ks) + a_kofs;
            uint32_t colb = (uint32_t)(32 * ks) + b_kofs;

            uint32_t B[8];
            #pragma unroll
            for (int pp = 0; pp < 2; pp++)
                ldm4(sbase + OFF_WH + b_rb[pp] + (colb ^ b_xor),
                     B[4 * pp], B[4 * pp + 1], B[4 * pp + 2], B[4 * pp + 3]);

            #pragma unroll
            for (int mb = 0; mb < 2; mb++) {
                uint32_t ahb = stage + a_rb + (uint32_t)mb * 2048u;
                ldm4(ahb + (cola ^ a_xor0), Ah[mb][0], Ah[mb][1], Ah[mb][2], Ah[mb][3]);
                uint32_t al0, al1, al2, al3;
                ldm4(ahb + 16384u + (cola ^ a_xor0), al0, al1, al2, al3);
                #pragma unroll
                for (int g = 0; g < 4; g++)
                    mma_bf16(acc[mb][g], Ah[mb][0], Ah[mb][1], Ah[mb][2], Ah[mb][3],
                             B[2 * g], B[2 * g + 1]);
                #pragma unroll
                for (int g = 0; g < 4; g++)
                    mma_bf16(acc[mb][g], al0, al1, al2, al3, B[2 * g], B[2 * g + 1]);
            }

            #pragma unroll
            for (int pp = 0; pp < 2; pp++)
                ldm4(sbase + OFF_WL + b_rb[pp] + (colb ^ b_xor),
                     B[4 * pp], B[4 * pp + 1], B[4 * pp + 2], B[4 * pp + 3]);

            #pragma unroll
            for (int mb = 0; mb < 2; mb++)
                #pragma unroll
                for (int g = 0; g < 4; g++)
                    mma_bf16(acc[mb][g], Ah[mb][0], Ah[mb][1], Ah[mb][2], Ah[mb][3],
                             B[2 * g], B[2 * g + 1]);
        }
        __syncthreads();   // stage-s reads done before refill at i+2

        // ---- scatter: 8 consecutive couts per lane, 4 rule-rows ----
        const int cbase = 16 * tq + 8 * h;
        #pragma unroll
        for (int mb = 0; mb < 2; mb++) {
            int rg1 = t0 * TILE + rrow + 16 * mb;
            int rg2 = rg1 + 8;
            int o1 = (rg1 < RR) ? __ldg(&out_idx[k * RR + rg1]) : -1;
            int o2 = (rg2 < RR) ? __ldg(&out_idx[k * RR + rg2]) : -1;
            if (o1 >= 0) {
                float* b = out + (size_t)o1 * COUT + cbase;
                red4(b,     acc[mb][0].x, acc[mb][0].y, acc[mb][1].x, acc[mb][1].y);
                red4(b + 4, acc[mb][2].x, acc[mb][2].y, acc[mb][3].x, acc[mb][3].y);
            }
            if (o2 >= 0) {
                float* b = out + (size_t)o2 * COUT + cbase;
                red4(b,     acc[mb][0].z, acc[mb][0].w, acc[mb][1].z, acc[mb][1].w);
                red4(b + 4, acc[mb][2].z, acc[mb][2].w, acc[mb][3].z, acc[mb][3].w);
            }
        }
        s ^= 1;
    }
}

extern "C" void kernel_launch(void* const* d_in, const int* in_sizes, int n_in,
                              void* d_out, int out_size)
{
    const float* x       = (const float*)d_in[0];
    const float* w       = (const float*)d_in[1];
    const float* bias    = (const float*)d_in[2];
    const int*   in_idx  = (const int*)d_in[3];
    const int*   out_idx = (const int*)d_in[4];
    float*       out     = (float*)d_out;

    split_x_kernel<<<(NIN * 8 + 255) / 256, 256>>>(x);
    split_w_kernel<<<(KK * CIN * COUT + 255) / 256, 256>>>(w);

    {
        int n4 = NOUT * (COUT / 4);
        init_out_kernel<<<(n4 + 255) / 256, 256>>>((float4*)out, (const float4*)bias);
    }

    cudaFuncSetAttribute(sparse_mma_kernel,
                         cudaFuncAttributeMaxDynamicSharedMemorySize, SMEM_BYTES);
    dim3 grid(NBX, KK);
    sparse_mma_kernel<<<grid, THREADS, SMEM_BYTES>>>(in_idx, out_idx, out);
}

// round 9
// speedup vs baseline: 1.2944x; 1.0801x over previous
#include <cuda_runtime.h>
#include <cuda_bf16.h>
#include <cstdint>

// Problem constants
#define KK   27
#define RR   50000
#define CIN  64
#define COUT 64
#define NIN  150000
#define NOUT 150000

#define TILE    128
#define NTILES  ((RR + TILE - 1) / TILE)      // 391
#define NPAIRS  ((NTILES + 1) / 2)            // 196
#define PPB     4                             // tile-pairs per block
#define NBX     ((NPAIRS + PPB - 1) / PPB)    // 49 (49*4 == 196 exactly)
#define THREADS 512

// SMEM: W(hi|lo) 16K, then 3 stages x 64K (stage = 2 tiles x (AH 16K | AL 16K))
#define OFF_WH   0u
#define OFF_WL   8192u
#define OFF_A    16384u
#define STG_B    65536u
#define SMEM_BYTES (16384u + 3u * STG_B)      // 212992

// ---- global scratch ----------------------------------------------------------
__device__ __align__(16) unsigned short g_xsplit[(size_t)NIN * 128];   // [hi64|lo64]
__device__ __align__(16) unsigned short g_wsplit[(size_t)KK * 8192];   // wh|wl swizzled

// ---- helpers -------------------------------------------------------------------
__device__ __forceinline__ uint32_t smem_u32(const void* p) {
    uint32_t a;
    asm("{ .reg .u64 t; cvta.to.shared.u64 t, %1; cvt.u32.u64 %0, t; }" : "=r"(a) : "l"(p));
    return a;
}
__device__ __forceinline__ void ldm4(uint32_t addr, uint32_t& r0, uint32_t& r1,
                                     uint32_t& r2, uint32_t& r3) {
    asm volatile("ldmatrix.sync.aligned.m8n8.x4.shared.b16 {%0,%1,%2,%3}, [%4];"
                 : "=r"(r0), "=r"(r1), "=r"(r2), "=r"(r3) : "r"(addr));
}
__device__ __forceinline__ void mma_bf16(float4& d,
                                         uint32_t a0, uint32_t a1, uint32_t a2, uint32_t a3,
                                         uint32_t b0, uint32_t b1) {
    asm volatile("mma.sync.aligned.m16n8k16.row.col.f32.bf16.bf16.f32 "
                 "{%0,%1,%2,%3}, {%4,%5,%6,%7}, {%8,%9}, {%0,%1,%2,%3};"
                 : "+f"(d.x), "+f"(d.y), "+f"(d.z), "+f"(d.w)
                 : "r"(a0), "r"(a1), "r"(a2), "r"(a3), "r"(b0), "r"(b1));
}
__device__ __forceinline__ void red4(float* p, float a, float b, float c, float d) {
    asm volatile("red.global.add.v4.f32 [%0], {%1, %2, %3, %4};"
                 :: "l"(p), "f"(a), "f"(b), "f"(c), "f"(d) : "memory");
}
__device__ __forceinline__ void split_bf16(float v, unsigned short& h, unsigned short& l) {
    __nv_bfloat16 bh = __float2bfloat16(v);
    float fh = __bfloat162float(bh);
    __nv_bfloat16 bl = __float2bfloat16(v - fh);
    h = *reinterpret_cast<unsigned short*>(&bh);
    l = *reinterpret_cast<unsigned short*>(&bl);
}

// ---- fused precompute: split x, split+permute+swizzle W, out = bias -------------
__global__ void precompute_kernel(const float* __restrict__ x,
                                  const float* __restrict__ w,
                                  const float4* __restrict__ bias4,
                                  float4* __restrict__ out4)
{
    int t = blockIdx.x * blockDim.x + threadIdx.x;

    if (t < NIN * 8) {              // split x: 8 floats per thread
        int row = t >> 3, c8 = t & 7;
        const float4* p = (const float4*)(x + (size_t)row * 64 + c8 * 8);
        float4 a = p[0], b = p[1];
        float v[8] = {a.x, a.y, a.z, a.w, b.x, b.y, b.z, b.w};
        unsigned short hi[8], lo[8];
        #pragma unroll
        for (int j = 0; j < 8; j++) split_bf16(v[j], hi[j], lo[j]);
        *(uint4*)(g_xsplit + (size_t)row * 128 + c8 * 8)      = *(uint4*)hi;
        *(uint4*)(g_xsplit + (size_t)row * 128 + 64 + c8 * 8) = *(uint4*)lo;
    }

    if (t < KK * CIN * COUT) {      // split W; perm r gives consecutive-cout d-frags
        int k = t / 4096, rem = t - k * 4096;
        int c = rem >> 6, o = rem & 63;
        unsigned short h, l;
        split_bf16(w[t], h, l);
        int r = ((o >> 1) & 7) * 8 + 2 * (o >> 4) + (o & 1);
        uint32_t off = (uint32_t)r * 128 + (uint32_t)c * 2;
        uint32_t sw  = off ^ ((off >> 3) & 0x70);
        g_wsplit[(size_t)k * 8192 + (sw >> 1)]        = h;
        g_wsplit[(size_t)k * 8192 + 4096 + (sw >> 1)] = l;
    }

    if (t < NOUT * (COUT / 4)) {    // out = bias broadcast
        out4[t] = bias4[t & (COUT / 4 - 1)];
    }
}

// ---- async gather of one tile-pair into stage sidx (512 threads) -----------------
__device__ __forceinline__ void gather_pair_async(uint32_t sbase, int sidx, int t0, int k,
                                                  const int* __restrict__ in_idx, int tid)
{
    const int gchunk = tid & 7;     // 16B chunk within 128B half-row
    const int gid    = tid >> 3;    // 0..63
    #pragma unroll
    for (int it = 0; it < 8; it++) {
        int hid  = it * 64 + gid;          // 0..511
        int tt   = hid >> 8;
        int rl   = (hid >> 1) & 127;
        int half = hid & 1;
        int rg   = (t0 + tt) * TILE + rl;
        if (rg < RR) {
            int gi = __ldg(&in_idx[k * RR + rg]);   // broadcast across 8 lanes
            const void* src = (const char*)(g_xsplit + (size_t)gi * 128 + half * 64)
                            + gchunk * 16;
            uint32_t off = (uint32_t)rl * 128 + gchunk * 16;
            uint32_t sw  = off ^ ((off >> 3) & 0x70);
            uint32_t dst = sbase + OFF_A + (uint32_t)sidx * STG_B
                         + (uint32_t)tt * 32768u + (uint32_t)half * 16384u + sw;
            asm volatile("cp.async.cg.shared.global [%0], [%1], 16;"
                         :: "r"(dst), "l"(src) : "memory");
        }
    }
    asm volatile("cp.async.commit_group;" ::: "memory");
}

// ---- main: 3-stage pipeline, B-frags in registers, one sync per pair -------------
extern "C" __global__ void __launch_bounds__(THREADS, 1)
sparse_mma_kernel(const int* __restrict__ in_idx,
                  const int* __restrict__ out_idx,
                  float*     __restrict__ out)
{
    extern __shared__ __align__(1024) char smem[];
    const uint32_t sbase = smem_u32(smem);
    const int tid  = threadIdx.x;
    const int lane = tid & 31;
    const int wrp  = tid >> 5;          // 0..15
    const int k    = blockIdx.y;
    const int pair0 = blockIdx.x * PPB;

    // prologue: gathers for pairs 0,1 into stages 0,1; then stage W
    gather_pair_async(sbase, 0, pair0 * 2, k, in_idx, tid);
    gather_pair_async(sbase, 1, (pair0 + 1) * 2, k, in_idx, tid);
    {
        const uint4* wg  = (const uint4*)(g_wsplit + (size_t)k * 8192);
        uint4*       wsm = (uint4*)(smem + OFF_WH);
        #pragma unroll
        for (int i = tid; i < 1024; i += THREADS) wsm[i] = wg[i];
    }
    __syncthreads();   // W visible for B-frag ldmatrix

    // warp roles: n-half h, rule-slice s8 (32 rules = 2 m16 blocks in tile tts)
    const int h   = wrp & 1;
    const int s8  = wrp >> 1;
    const int tts = s8 >> 2;
    const int mrow0 = (s8 & 3) * 32 + (lane & 15);

    // ---- B fragments: load ONCE into registers (whole block reuses W) ----
    uint32_t Bh[4][8], Bl[4][8];
    {
        const uint32_t b_xor  = (uint32_t)((lane & 7) << 4);
        const uint32_t b_kofs = (uint32_t)(((lane >> 3) & 1) * 16);
        uint32_t b_rb[2];
        #pragma unroll
        for (int pp = 0; pp < 2; pp++) {
            int p = 2 * h + pp;
            b_rb[pp] = (uint32_t)(((2 * p + (lane >> 4)) * 8 + (lane & 7)) * 128);
        }
        #pragma unroll
        for (int ks = 0; ks < 4; ks++) {
            uint32_t colb = (uint32_t)(32 * ks) + b_kofs;
            #pragma unroll
            for (int pp = 0; pp < 2; pp++) {
                ldm4(sbase + OFF_WH + b_rb[pp] + (colb ^ b_xor),
                     Bh[ks][4 * pp], Bh[ks][4 * pp + 1], Bh[ks][4 * pp + 2], Bh[ks][4 * pp + 3]);
                ldm4(sbase + OFF_WL + b_rb[pp] + (colb ^ b_xor),
                     Bl[ks][4 * pp], Bl[ks][4 * pp + 1], Bl[ks][4 * pp + 2], Bl[ks][4 * pp + 3]);
            }
        }
    }

    // A ldmatrix addressing (per mb: +16 rows = +2048B)
    const uint32_t a_xor0 = (uint32_t)((mrow0 & 7) << 4);
    const uint32_t a_rb   = (uint32_t)tts * 32768u + (uint32_t)mrow0 * 128u;
    const uint32_t a_kofs = (uint32_t)(((lane >> 4) & 1) * 16);

    // epilogue constants
    const int tq   = lane & 3;
    const int rrow = 32 * s8 + (lane >> 2);
    const int cbase = 16 * tq + 8 * h;

    #pragma unroll 1
    for (int i = 0; i < PPB; i++) {
        int t0 = (pair0 + i) * 2;

        // wait for this pair's gather group, then block-wide visibility
        if (i < PPB - 1) asm volatile("cp.async.wait_group 1;" ::: "memory");
        else             asm volatile("cp.async.wait_group 0;" ::: "memory");
        __syncthreads();   // also: everyone finished reading stage (i+2)%3 last round

        // issue gather for pair i+2 into stage (i+2)%3
        if (i + 2 < PPB)
            gather_pair_async(sbase, (i + 2) % 3, (pair0 + i + 2) * 2, k, in_idx, tid);

        // ---- MMA on stage i%3 (B from registers) ----
        float4 acc[2][4];
        #pragma unroll
        for (int mb = 0; mb < 2; mb++)
            #pragma unroll
            for (int g = 0; g < 4; g++) acc[mb][g] = make_float4(0.f, 0.f, 0.f, 0.f);

        const uint32_t stage = sbase + OFF_A + (uint32_t)(i % 3) * STG_B;

        #pragma unroll
        for (int ks = 0; ks < 4; ks++) {
            uint32_t cola = (uint32_t)(32 * ks) + a_kofs;
            #pragma unroll
            for (int mb = 0; mb < 2; mb++) {
                uint32_t ahb = stage + a_rb + (uint32_t)mb * 2048u;
                uint32_t ah0, ah1, ah2, ah3, al0, al1, al2, al3;
                ldm4(ahb + (cola ^ a_xor0), ah0, ah1, ah2, ah3);
                ldm4(ahb + 16384u + (cola ^ a_xor0), al0, al1, al2, al3);
                #pragma unroll
                for (int g = 0; g < 4; g++)
                    mma_bf16(acc[mb][g], ah0, ah1, ah2, ah3, Bh[ks][2 * g], Bh[ks][2 * g + 1]);
                #pragma unroll
                for (int g = 0; g < 4; g++)
                    mma_bf16(acc[mb][g], al0, al1, al2, al3, Bh[ks][2 * g], Bh[ks][2 * g + 1]);
                #pragma unroll
                for (int g = 0; g < 4; g++)
                    mma_bf16(acc[mb][g], ah0, ah1, ah2, ah3, Bl[ks][2 * g], Bl[ks][2 * g + 1]);
            }
        }

        // ---- scatter: 8 consecutive couts per lane, 4 rule-rows ----
        #pragma unroll
        for (int mb = 0; mb < 2; mb++) {
            int rg1 = t0 * TILE + rrow + 16 * mb;
            int rg2 = rg1 + 8;
            int o1 = (rg1 < RR) ? __ldg(&out_idx[k * RR + rg1]) : -1;
            int o2 = (rg2 < RR) ? __ldg(&out_idx[k * RR + rg2]) : -1;
            if (o1 >= 0) {
                float* b = out + (size_t)o1 * COUT + cbase;
                red4(b,     acc[mb][0].x, acc[mb][0].y, acc[mb][1].x, acc[mb][1].y);
                red4(b + 4, acc[mb][2].x, acc[mb][2].y, acc[mb][3].x, acc[mb][3].y);
            }
            if (o2 >= 0) {
                float* b = out + (size_t)o2 * COUT + cbase;
                red4(b,     acc[mb][0].z, acc[mb][0].w, acc[mb][1].z, acc[mb][1].w);
                red4(b + 4, acc[mb][2].z, acc[mb][2].w, acc[mb][3].z, acc[mb][3].w);
            }
        }
    }
}

extern "C" void kernel_launch(void* const* d_in, const int* in_sizes, int n_in,
                              void* d_out, int out_size)
{
    const float* x       = (const float*)d_in[0];
    const float* w       = (const float*)d_in[1];
    const float* bias    = (const float*)d_in[2];
    const int*   in_idx  = (const int*)d_in[3];
    const int*   out_idx = (const int*)d_in[4];
    float*       out     = (float*)d_out;

    {   // fused: split x, split W, out = bias
        int nmax = NOUT * (COUT / 4);   // largest range (2.4M)
        precompute_kernel<<<(nmax + 255) / 256, 256>>>(x, w, (const float4*)bias,
                                                       (float4*)out);
    }

    cudaFuncSetAttribute(sparse_mma_kernel,
                         cudaFuncAttributeMaxDynamicSharedMemorySize, SMEM_BYTES);
    dim3 grid(NBX, KK);
    sparse_mma_kernel<<<grid, THREADS, SMEM_BYTES>>>(in_idx, out_idx, out);
}

// round 10
// speedup vs baseline: 1.3309x; 1.0282x over previous
#include <cuda_runtime.h>
#include <cuda_bf16.h>
#include <cstdint>

// Problem constants
#define KK   27
#define RR   50000
#define CIN  64
#define COUT 64
#define NIN  150000
#define NOUT 150000

#define TILE    128
#define NTILES  ((RR + TILE - 1) / TILE)      // 391
#define TPB     14                            // tiles per block
#define TPG     7                             // tiles per group (2 groups)
#define NBX     ((NTILES + TPB - 1) / TPB)    // 28
#define THREADS 512

// SMEM: W(hi|lo) 16K, then per-group 3 stages x 32K (stage = AH 16K | AL 16K)
#define OFF_WH  0u
#define OFF_WL  8192u
#define OFF_A   16384u
#define GRP_B   98304u      // 3 * 32768
#define STG_SZ  32768u
#define SMEM_BYTES (16384u + 2u * GRP_B)      // 212992

// ---- global scratch ----------------------------------------------------------
__device__ __align__(16) unsigned short g_xsplit[(size_t)NIN * 128];   // [hi64|lo64]
__device__ __align__(16) unsigned short g_wsplit[(size_t)KK * 8192];   // wh|wl swizzled

// ---- helpers -------------------------------------------------------------------
__device__ __forceinline__ uint32_t smem_u32(const void* p) {
    uint32_t a;
    asm("{ .reg .u64 t; cvta.to.shared.u64 t, %1; cvt.u32.u64 %0, t; }" : "=r"(a) : "l"(p));
    return a;
}
__device__ __forceinline__ void ldm4(uint32_t addr, uint32_t& r0, uint32_t& r1,
                                     uint32_t& r2, uint32_t& r3) {
    asm volatile("ldmatrix.sync.aligned.m8n8.x4.shared.b16 {%0,%1,%2,%3}, [%4];"
                 : "=r"(r0), "=r"(r1), "=r"(r2), "=r"(r3) : "r"(addr));
}
__device__ __forceinline__ void mma_bf16(float4& d,
                                         uint32_t a0, uint32_t a1, uint32_t a2, uint32_t a3,
                                         uint32_t b0, uint32_t b1) {
    asm volatile("mma.sync.aligned.m16n8k16.row.col.f32.bf16.bf16.f32 "
                 "{%0,%1,%2,%3}, {%4,%5,%6,%7}, {%8,%9}, {%0,%1,%2,%3};"
                 : "+f"(d.x), "+f"(d.y), "+f"(d.z), "+f"(d.w)
                 : "r"(a0), "r"(a1), "r"(a2), "r"(a3), "r"(b0), "r"(b1));
}
__device__ __forceinline__ void red4(float* p, float a, float b, float c, float d) {
    asm volatile("red.global.add.v4.f32 [%0], {%1, %2, %3, %4};"
                 :: "l"(p), "f"(a), "f"(b), "f"(c), "f"(d) : "memory");
}
__device__ __forceinline__ void bar_grp(int id) {
    asm volatile("bar.sync %0, 256;" :: "r"(id) : "memory");
}
__device__ __forceinline__ void split_bf16(float v, unsigned short& h, unsigned short& l) {
    __nv_bfloat16 bh = __float2bfloat16(v);
    float fh = __bfloat162float(bh);
    __nv_bfloat16 bl = __float2bfloat16(v - fh);
    h = *reinterpret_cast<unsigned short*>(&bh);
    l = *reinterpret_cast<unsigned short*>(&bl);
}

// ---- fused precompute: split x, split+permute+swizzle W, out = bias -------------
__global__ void precompute_kernel(const float* __restrict__ x,
                                  const float* __restrict__ w,
                                  const float4* __restrict__ bias4,
                                  float4* __restrict__ out4)
{
    int t = blockIdx.x * blockDim.x + threadIdx.x;

    if (t < NIN * 8) {              // split x: 8 floats per thread
        int row = t >> 3, c8 = t & 7;
        const float4* p = (const float4*)(x + (size_t)row * 64 + c8 * 8);
        float4 a = p[0], b = p[1];
        float v[8] = {a.x, a.y, a.z, a.w, b.x, b.y, b.z, b.w};
        unsigned short hi[8], lo[8];
        #pragma unroll
        for (int j = 0; j < 8; j++) split_bf16(v[j], hi[j], lo[j]);
        *(uint4*)(g_xsplit + (size_t)row * 128 + c8 * 8)      = *(uint4*)hi;
        *(uint4*)(g_xsplit + (size_t)row * 128 + 64 + c8 * 8) = *(uint4*)lo;
    }

    if (t < KK * CIN * COUT) {      // split W; perm r gives consecutive-cout d-frags
        int k = t / 4096, rem = t - k * 4096;
        int c = rem >> 6, o = rem & 63;
        unsigned short h, l;
        split_bf16(w[t], h, l);
        int r = ((o >> 1) & 7) * 8 + 2 * (o >> 4) + (o & 1);
        uint32_t off = (uint32_t)r * 128 + (uint32_t)c * 2;
        uint32_t sw  = off ^ ((off >> 3) & 0x70);
        g_wsplit[(size_t)k * 8192 + (sw >> 1)]        = h;
        g_wsplit[(size_t)k * 8192 + 4096 + (sw >> 1)] = l;
    }

    if (t < NOUT * (COUT / 4)) {    // out = bias broadcast
        out4[t] = bias4[t & (COUT / 4 - 1)];
    }
}

// ---- async gather of ONE tile into group g's stage sidx (256 threads) -----------
__device__ __forceinline__ void gather_tile_async(uint32_t sbase, int g, int sidx,
                                                  int t, int k,
                                                  const int* __restrict__ in_idx, int tid)
{
    const int gchunk = tid & 7;          // 16B chunk within 128B half-row
    const int gi8    = (tid >> 3) & 31;  // half-row group within 256-thread group
    const uint32_t base = sbase + OFF_A + (uint32_t)g * GRP_B + (uint32_t)sidx * STG_SZ;
    #pragma unroll
    for (int it = 0; it < 8; it++) {
        int hid  = it * 32 + gi8;        // 0..255
        int rl   = hid >> 1;
        int half = hid & 1;
        int rg   = t * TILE + rl;
        if (rg < RR) {
            int gi = __ldg(&in_idx[k * RR + rg]);   // broadcast across 8 lanes
            const void* src = (const char*)(g_xsplit + (size_t)gi * 128 + half * 64)
                            + gchunk * 16;
            uint32_t off = (uint32_t)rl * 128 + gchunk * 16;
            uint32_t sw  = off ^ ((off >> 3) & 0x70);
            uint32_t dst = base + (uint32_t)half * 16384u + sw;
            asm volatile("cp.async.cg.shared.global [%0], [%1], 16;"
                         :: "r"(dst), "l"(src) : "memory");
        }
    }
    asm volatile("cp.async.commit_group;" ::: "memory");
}

// ---- main: 2 independent 8-warp pipelines, B-frags in regs, 3-stage cp.async -----
extern "C" __global__ void __launch_bounds__(THREADS, 1)
sparse_mma_kernel(const int* __restrict__ in_idx,
                  const int* __restrict__ out_idx,
                  float*     __restrict__ out)
{
    extern __shared__ __align__(1024) char smem[];
    const uint32_t sbase = smem_u32(smem);
    const int tid  = threadIdx.x;
    const int lane = tid & 31;
    const int wrp  = tid >> 5;          // 0..15
    const int g    = wrp >> 3;          // group 0/1
    const int wg   = wrp & 7;           // warp within group
    const int gt   = tid & 255;         // thread within group
    const int k    = blockIdx.y;
    const int tbase = blockIdx.x * TPB;

    // prologue: each group issues gathers for its first 2 tiles, then stage W
    gather_tile_async(sbase, g, 0, tbase + g,     k, in_idx, gt);
    gather_tile_async(sbase, g, 1, tbase + 2 + g, k, in_idx, gt);
    {
        const uint4* wgp = (const uint4*)(g_wsplit + (size_t)k * 8192);
        uint4*       wsm = (uint4*)(smem + OFF_WH);
        #pragma unroll
        for (int i = tid; i < 1024; i += THREADS) wsm[i] = wgp[i];
    }
    __syncthreads();   // W visible for B-frag ldmatrix

    // warp roles within group: n-half h, rule-slice s8 (32 rules each)
    const int h   = wg & 1;
    const int s8  = wg >> 1;            // 0..3
    const int mrow0 = s8 * 32 + (lane & 15);

    // ---- B fragments: load ONCE into registers ----
    uint32_t Bh[4][8], Bl[4][8];
    {
        const uint32_t b_xor  = (uint32_t)((lane & 7) << 4);
        const uint32_t b_kofs = (uint32_t)(((lane >> 3) & 1) * 16);
        uint32_t b_rb[2];
        #pragma unroll
        for (int pp = 0; pp < 2; pp++) {
            int p = 2 * h + pp;
            b_rb[pp] = (uint32_t)(((2 * p + (lane >> 4)) * 8 + (lane & 7)) * 128);
        }
        #pragma unroll
        for (int ks = 0; ks < 4; ks++) {
            uint32_t colb = (uint32_t)(32 * ks) + b_kofs;
            #pragma unroll
            for (int pp = 0; pp < 2; pp++) {
                ldm4(sbase + OFF_WH + b_rb[pp] + (colb ^ b_xor),
                     Bh[ks][4 * pp], Bh[ks][4 * pp + 1], Bh[ks][4 * pp + 2], Bh[ks][4 * pp + 3]);
                ldm4(sbase + OFF_WL + b_rb[pp] + (colb ^ b_xor),
                     Bl[ks][4 * pp], Bl[ks][4 * pp + 1], Bl[ks][4 * pp + 2], Bl[ks][4 * pp + 3]);
            }
        }
    }

    // A ldmatrix addressing (per mb: +16 rows = +2048B)
    const uint32_t a_xor0 = (uint32_t)((mrow0 & 7) << 4);
    const uint32_t a_rb   = (uint32_t)mrow0 * 128u;
    const uint32_t a_kofs = (uint32_t)(((lane >> 4) & 1) * 16);
    const uint32_t gbase  = sbase + OFF_A + (uint32_t)g * GRP_B;

    // epilogue constants
    const int tq    = lane & 3;
    const int rrow  = 32 * s8 + (lane >> 2);
    const int cbase = 16 * tq + 8 * h;
    const int barid = 1 + g;

    #pragma unroll 1
    for (int i = 0; i < TPG; i++) {
        int t = tbase + 2 * i + g;

        // wait for this tile's gather, group-local visibility barrier
        if (i < TPG - 1) asm volatile("cp.async.wait_group 1;" ::: "memory");
        else             asm volatile("cp.async.wait_group 0;" ::: "memory");
        bar_grp(barid);   // also: group finished reading stage (i-1)%3 last iter

        // issue gather for tile i+2 into stage (i+2)%3
        if (i + 2 < TPG)
            gather_tile_async(sbase, g, (i + 2) % 3, tbase + 2 * (i + 2) + g, k, in_idx, gt);

        // ---- MMA on stage i%3 (B from registers) ----
        float4 acc[2][4];
        #pragma unroll
        for (int mb = 0; mb < 2; mb++)
            #pragma unroll
            for (int q = 0; q < 4; q++) acc[mb][q] = make_float4(0.f, 0.f, 0.f, 0.f);

        const uint32_t stage = gbase + (uint32_t)(i % 3) * STG_SZ;

        #pragma unroll
        for (int ks = 0; ks < 4; ks++) {
            uint32_t cola = (uint32_t)(32 * ks) + a_kofs;
            #pragma unroll
            for (int mb = 0; mb < 2; mb++) {
                uint32_t ahb = stage + a_rb + (uint32_t)mb * 2048u;
                uint32_t ah0, ah1, ah2, ah3, al0, al1, al2, al3;
                ldm4(ahb + (cola ^ a_xor0), ah0, ah1, ah2, ah3);
                ldm4(ahb + 16384u + (cola ^ a_xor0), al0, al1, al2, al3);
                #pragma unroll
                for (int q = 0; q < 4; q++)
                    mma_bf16(acc[mb][q], ah0, ah1, ah2, ah3, Bh[ks][2 * q], Bh[ks][2 * q + 1]);
                #pragma unroll
                for (int q = 0; q < 4; q++)
                    mma_bf16(acc[mb][q], al0, al1, al2, al3, Bh[ks][2 * q], Bh[ks][2 * q + 1]);
                #pragma unroll
                for (int q = 0; q < 4; q++)
                    mma_bf16(acc[mb][q], ah0, ah1, ah2, ah3, Bl[ks][2 * q], Bl[ks][2 * q + 1]);
            }
        }

        // ---- scatter: 8 consecutive couts per lane, 4 rule-rows ----
        #pragma unroll
        for (int mb = 0; mb < 2; mb++) {
            int rg1 = t * TILE + rrow + 16 * mb;
            int rg2 = rg1 + 8;
            int o1 = (rg1 < RR) ? __ldg(&out_idx[k * RR + rg1]) : -1;
            int o2 = (rg2 < RR) ? __ldg(&out_idx[k * RR + rg2]) : -1;
            if (o1 >= 0) {
                float* b = out + (size_t)o1 * COUT + cbase;
                red4(b,     acc[mb][0].x, acc[mb][0].y, acc[mb][1].x, acc[mb][1].y);
                red4(b + 4, acc[mb][2].x, acc[mb][2].y, acc[mb][3].x, acc[mb][3].y);
            }
            if (o2 >= 0) {
                float* b = out + (size_t)o2 * COUT + cbase;
                red4(b,     acc[mb][0].z, acc[mb][0].w, acc[mb][1].z, acc[mb][1].w);
                red4(b + 4, acc[mb][2].z, acc[mb][2].w, acc[mb][3].z, acc[mb][3].w);
            }
        }
    }
}

extern "C" void kernel_launch(void* const* d_in, const int* in_sizes, int n_in,
                              void* d_out, int out_size)
{
    const float* x       = (const float*)d_in[0];
    const float* w       = (const float*)d_in[1];
    const float* bias    = (const float*)d_in[2];
    const int*   in_idx  = (const int*)d_in[3];
    const int*   out_idx = (const int*)d_in[4];
    float*       out     = (float*)d_out;

    {   // fused: split x, split W, out = bias
        int nmax = NOUT * (COUT / 4);   // largest range (2.4M)
        precompute_kernel<<<(nmax + 255) / 256, 256>>>(x, w, (const float4*)bias,
                                                       (float4*)out);
    }

    cudaFuncSetAttribute(sparse_mma_kernel,
                         cudaFuncAttributeMaxDynamicSharedMemorySize, SMEM_BYTES);
    dim3 grid(NBX, KK);
    sparse_mma_kernel<<<grid, THREADS, SMEM_BYTES>>>(in_idx, out_idx, out);
}

// round 11
// speedup vs baseline: 1.7326x; 1.3018x over previous
#include <cuda_runtime.h>
#include <cuda_bf16.h>
#include <cstdint>

// Problem constants
#define KK   27
#define RR   50000
#define CIN  64
#define COUT 64
#define NIN  150000
#define NOUT 150000

#define TILE    128
#define NTILES  ((RR + TILE - 1) / TILE)      // 391
#define TPB     14                            // tiles per block
#define TPG     7                             // tiles per group (2 groups)
#define NBX     ((NTILES + TPB - 1) / TPB)    // 28
#define THREADS 512

// SMEM: W(hi|lo) 16K, then per-group 3 stages x 32K (stage = AH 16K | AL 16K)
#define OFF_WH  0u
#define OFF_WL  8192u
#define OFF_A   16384u
#define GRP_B   98304u      // 3 * 32768
#define STG_SZ  32768u
#define SMEM_BYTES (16384u + 2u * GRP_B)      // 212992

// ---- global scratch ----------------------------------------------------------
__device__ __align__(16) unsigned short g_xsplit[(size_t)NIN * 128];   // [hi64|lo64]
__device__ __align__(16) unsigned short g_wsplit[(size_t)KK * 8192];   // wh|wl swizzled

// ---- helpers -------------------------------------------------------------------
__device__ __forceinline__ uint32_t smem_u32(const void* p) {
    uint32_t a;
    asm("{ .reg .u64 t; cvta.to.shared.u64 t, %1; cvt.u32.u64 %0, t; }" : "=r"(a) : "l"(p));
    return a;
}
__device__ __forceinline__ void ldm4(uint32_t addr, uint32_t& r0, uint32_t& r1,
                                     uint32_t& r2, uint32_t& r3) {
    asm volatile("ldmatrix.sync.aligned.m8n8.x4.shared.b16 {%0,%1,%2,%3}, [%4];"
                 : "=r"(r0), "=r"(r1), "=r"(r2), "=r"(r3) : "r"(addr));
}
__device__ __forceinline__ void mma_bf16(float4& d,
                                         uint32_t a0, uint32_t a1, uint32_t a2, uint32_t a3,
                                         uint32_t b0, uint32_t b1) {
    asm volatile("mma.sync.aligned.m16n8k16.row.col.f32.bf16.bf16.f32 "
                 "{%0,%1,%2,%3}, {%4,%5,%6,%7}, {%8,%9}, {%0,%1,%2,%3};"
                 : "+f"(d.x), "+f"(d.y), "+f"(d.z), "+f"(d.w)
                 : "r"(a0), "r"(a1), "r"(a2), "r"(a3), "r"(b0), "r"(b1));
}
__device__ __forceinline__ void red4(float* p, float a, float b, float c, float d) {
    asm volatile("red.global.add.v4.f32 [%0], {%1, %2, %3, %4};"
                 :: "l"(p), "f"(a), "f"(b), "f"(c), "f"(d) : "memory");
}
__device__ __forceinline__ void bar_grp(int id) {
    asm volatile("bar.sync %0, 256;" :: "r"(id) : "memory");
}
__device__ __forceinline__ void split_bf16(float v, unsigned short& h, unsigned short& l) {
    __nv_bfloat16 bh = __float2bfloat16(v);
    float fh = __bfloat162float(bh);
    __nv_bfloat16 bl = __float2bfloat16(v - fh);
    h = *reinterpret_cast<unsigned short*>(&bh);
    l = *reinterpret_cast<unsigned short*>(&bl);
}

// ---- fused precompute: split x, split+permute+swizzle W, out = bias -------------
__global__ void precompute_kernel(const float* __restrict__ x,
                                  const float* __restrict__ w,
                                  const float4* __restrict__ bias4,
                                  float4* __restrict__ out4)
{
    int t = blockIdx.x * blockDim.x + threadIdx.x;

    if (t < NIN * 8) {              // split x: 8 floats per thread
        int row = t >> 3, c8 = t & 7;
        const float4* p = (const float4*)(x + (size_t)row * 64 + c8 * 8);
        float4 a = p[0], b = p[1];
        float v[8] = {a.x, a.y, a.z, a.w, b.x, b.y, b.z, b.w};
        unsigned short hi[8], lo[8];
        #pragma unroll
        for (int j = 0; j < 8; j++) split_bf16(v[j], hi[j], lo[j]);
        *(uint4*)(g_xsplit + (size_t)row * 128 + c8 * 8)      = *(uint4*)hi;
        *(uint4*)(g_xsplit + (size_t)row * 128 + 64 + c8 * 8) = *(uint4*)lo;
    }

    if (t < KK * CIN * COUT) {      // split W; perm r gives consecutive-cout d-frags
        int k = t / 4096, rem = t - k * 4096;
        int c = rem >> 6, o = rem & 63;
        unsigned short h, l;
        split_bf16(w[t], h, l);
        int r = ((o >> 1) & 7) * 8 + 2 * (o >> 4) + (o & 1);
        uint32_t off = (uint32_t)r * 128 + (uint32_t)c * 2;
        uint32_t sw  = off ^ ((off >> 3) & 0x70);
        g_wsplit[(size_t)k * 8192 + (sw >> 1)]        = h;
        g_wsplit[(size_t)k * 8192 + 4096 + (sw >> 1)] = l;
    }

    if (t < NOUT * (COUT / 4)) {    // out = bias broadcast
        out4[t] = bias4[t & (COUT / 4 - 1)];
    }
}

// ---- prefetch 8 rule indices for a tile (this thread's gather slots) -------------
__device__ __forceinline__ void idx_prefetch(int t, int k, const int* __restrict__ in_idx,
                                             int gt, int* idxbuf)
{
    const int gi8 = (gt >> 3) & 31;
    #pragma unroll
    for (int it = 0; it < 8; it++) {
        int hid = it * 32 + gi8;
        int rl  = hid >> 1;
        int rg  = t * TILE + rl;
        idxbuf[it] = (rg < RR) ? __ldg(&in_idx[k * RR + rg]) : -1;
    }
}

// ---- async gather of ONE tile using prefetched indices ---------------------------
__device__ __forceinline__ void gather_tile_buf(uint32_t sbase, int g, int sidx,
                                                const int* idxbuf, int gt)
{
    const int gchunk = gt & 7;
    const int gi8    = (gt >> 3) & 31;
    const uint32_t base = sbase + OFF_A + (uint32_t)g * GRP_B + (uint32_t)sidx * STG_SZ;
    #pragma unroll
    for (int it = 0; it < 8; it++) {
        int hid  = it * 32 + gi8;
        int rl   = hid >> 1;
        int half = hid & 1;
        int gi   = idxbuf[it];
        if (gi >= 0) {
            const void* src = (const char*)(g_xsplit + (size_t)gi * 128 + half * 64)
                            + gchunk * 16;
            uint32_t off = (uint32_t)rl * 128 + gchunk * 16;
            uint32_t sw  = off ^ ((off >> 3) & 0x70);
            uint32_t dst = base + (uint32_t)half * 16384u + sw;
            asm volatile("cp.async.cg.shared.global [%0], [%1], 16;"
                         :: "r"(dst), "l"(src) : "memory");
        }
    }
    asm volatile("cp.async.commit_group;" ::: "memory");
}

// ---- main: 2 pipelines, B-frags in regs, idx prefetch, mb-outer MMA --------------
extern "C" __global__ void __launch_bounds__(THREADS, 1)
sparse_mma_kernel(const int* __restrict__ in_idx,
                  const int* __restrict__ out_idx,
                  float*     __restrict__ out)
{
    extern __shared__ __align__(1024) char smem[];
    const uint32_t sbase = smem_u32(smem);
    const int tid  = threadIdx.x;
    const int lane = tid & 31;
    const int wrp  = tid >> 5;          // 0..15
    const int g    = wrp >> 3;          // group 0/1
    const int wg   = wrp & 7;           // warp within group
    const int gt   = tid & 255;         // thread within group
    const int k    = blockIdx.y;
    const int tbase = blockIdx.x * TPB;

    int idxbuf[8];

    // prologue: gathers for first 2 tiles of this group (inline idx), stage W
    idx_prefetch(tbase + g, k, in_idx, gt, idxbuf);
    gather_tile_buf(sbase, g, 0, idxbuf, gt);
    idx_prefetch(tbase + 2 + g, k, in_idx, gt, idxbuf);
    gather_tile_buf(sbase, g, 1, idxbuf, gt);
    // preload indices for tile local-index 2 (issued at loop i=0)
    idx_prefetch(tbase + 4 + g, k, in_idx, gt, idxbuf);
    {
        const uint4* wgp = (const uint4*)(g_wsplit + (size_t)k * 8192);
        uint4*       wsm = (uint4*)(smem + OFF_WH);
        #pragma unroll
        for (int i = tid; i < 1024; i += THREADS) wsm[i] = wgp[i];
    }
    __syncthreads();   // W visible for B-frag ldmatrix

    // warp roles within group: n-half h, rule-slice s8 (32 rules each)
    const int h   = wg & 1;
    const int s8  = wg >> 1;            // 0..3
    const int mrow0 = s8 * 32 + (lane & 15);

    // ---- B fragments: load ONCE into registers ----
    uint32_t Bh[4][8], Bl[4][8];
    {
        const uint32_t b_xor  = (uint32_t)((lane & 7) << 4);
        const uint32_t b_kofs = (uint32_t)(((lane >> 3) & 1) * 16);
        uint32_t b_rb[2];
        #pragma unroll
        for (int pp = 0; pp < 2; pp++) {
            int p = 2 * h + pp;
            b_rb[pp] = (uint32_t)(((2 * p + (lane >> 4)) * 8 + (lane & 7)) * 128);
        }
        #pragma unroll
        for (int ks = 0; ks < 4; ks++) {
            uint32_t colb = (uint32_t)(32 * ks) + b_kofs;
            #pragma unroll
            for (int pp = 0; pp < 2; pp++) {
                ldm4(sbase + OFF_WH + b_rb[pp] + (colb ^ b_xor),
                     Bh[ks][4 * pp], Bh[ks][4 * pp + 1], Bh[ks][4 * pp + 2], Bh[ks][4 * pp + 3]);
                ldm4(sbase + OFF_WL + b_rb[pp] + (colb ^ b_xor),
                     Bl[ks][4 * pp], Bl[ks][4 * pp + 1], Bl[ks][4 * pp + 2], Bl[ks][4 * pp + 3]);
            }
        }
    }

    // A ldmatrix addressing (per mb: +16 rows = +2048B)
    const uint32_t a_xor0 = (uint32_t)((mrow0 & 7) << 4);
    const uint32_t a_rb   = (uint32_t)mrow0 * 128u;
    const uint32_t a_kofs = (uint32_t)(((lane >> 4) & 1) * 16);
    const uint32_t gbase  = sbase + OFF_A + (uint32_t)g * GRP_B;

    // epilogue constants
    const int tq    = lane & 3;
    const int rrow  = 32 * s8 + (lane >> 2);
    const int cbase = 16 * tq + 8 * h;
    const int barid = 1 + g;

    #pragma unroll 1
    for (int i = 0; i < TPG; i++) {
        int t = tbase + 2 * i + g;

        // wait for this tile's gather, group-local visibility barrier
        if (i < TPG - 1) asm volatile("cp.async.wait_group 1;" ::: "memory");
        else             asm volatile("cp.async.wait_group 0;" ::: "memory");
        bar_grp(barid);   // also: group finished reading stage (i-1)%3 last iter

        // issue gather for tile i+2 (indices already in registers)
        if (i + 2 < TPG)
            gather_tile_buf(sbase, g, (i + 2) % 3, idxbuf, gt);

        // prefetch this tile's 4 output indices (hides under MMA below)
        int obuf[4];
        #pragma unroll
        for (int mb = 0; mb < 2; mb++) {
            int rg1 = t * TILE + rrow + 16 * mb;
            int rg2 = rg1 + 8;
            obuf[2 * mb]     = (rg1 < RR) ? __ldg(&out_idx[k * RR + rg1]) : -1;
            obuf[2 * mb + 1] = (rg2 < RR) ? __ldg(&out_idx[k * RR + rg2]) : -1;
        }
        // prefetch rule indices for tile i+3 (used 2 iterations from now)
        if (i + 3 < TPG)
            idx_prefetch(tbase + 2 * (i + 3) + g, k, in_idx, gt, idxbuf);

        // ---- MMA + scatter, mb-outer: mb=0's red4s overlap mb=1's MMA ----
        const uint32_t stage = gbase + (uint32_t)(i % 3) * STG_SZ;
        #pragma unroll
        for (int mb = 0; mb < 2; mb++) {
            float4 acc[4];
            #pragma unroll
            for (int q = 0; q < 4; q++) acc[q] = make_float4(0.f, 0.f, 0.f, 0.f);

            const uint32_t ahb = stage + a_rb + (uint32_t)mb * 2048u;
            #pragma unroll
            for (int ks = 0; ks < 4; ks++) {
                uint32_t cola = (uint32_t)(32 * ks) + a_kofs;
                uint32_t ah0, ah1, ah2, ah3, al0, al1, al2, al3;
                ldm4(ahb + (cola ^ a_xor0), ah0, ah1, ah2, ah3);
                ldm4(ahb + 16384u + (cola ^ a_xor0), al0, al1, al2, al3);
                #pragma unroll
                for (int q = 0; q < 4; q++)
                    mma_bf16(acc[q], ah0, ah1, ah2, ah3, Bh[ks][2 * q], Bh[ks][2 * q + 1]);
                #pragma unroll
                for (int q = 0; q < 4; q++)
                    mma_bf16(acc[q], al0, al1, al2, al3, Bh[ks][2 * q], Bh[ks][2 * q + 1]);
                #pragma unroll
                for (int q = 0; q < 4; q++)
                    mma_bf16(acc[q], ah0, ah1, ah2, ah3, Bl[ks][2 * q], Bl[ks][2 * q + 1]);
            }

            int o1 = obuf[2 * mb], o2 = obuf[2 * mb + 1];
            if (o1 >= 0) {
                float* b = out + (size_t)o1 * COUT + cbase;
                red4(b,     acc[0].x, acc[0].y, acc[1].x, acc[1].y);
                red4(b + 4, acc[2].x, acc[2].y, acc[3].x, acc[3].y);
            }
            if (o2 >= 0) {
                float* b = out + (size_t)o2 * COUT + cbase;
                red4(b,     acc[0].z, acc[0].w, acc[1].z, acc[1].w);
                red4(b + 4, acc[2].z, acc[2].w, acc[3].z, acc[3].w);
            }
        }
    }
}

extern "C" void kernel_launch(void* const* d_in, const int* in_sizes, int n_in,
                              void* d_out, int out_size)
{
    const float* x       = (const float*)d_in[0];
    const float* w       = (const float*)d_in[1];
    const float* bias    = (const float*)d_in[2];
    const int*   in_idx  = (const int*)d_in[3];
    const int*   out_idx = (const int*)d_in[4];
    float*       out     = (float*)d_out;

    {   // fused: split x, split W, out = bias
        int nmax = NOUT * (COUT / 4);   // largest range (2.4M)
        precompute_kernel<<<(nmax + 255) / 256, 256>>>(x, w, (const float4*)bias,
                                                       (float4*)out);
    }

    cudaFuncSetAttribute(sparse_mma_kernel,
                         cudaFuncAttributeMaxDynamicSharedMemorySize, SMEM_BYTES);
    dim3 grid(NBX, KK);
    sparse_mma_kernel<<<grid, THREADS, SMEM_BYTES>>>(in_idx, out_idx, out);
}

// round 12
// speedup vs baseline: 1.7753x; 1.0247x over previous
#include <cuda_runtime.h>
#include <cuda_bf16.h>
#include <cstdint>

// Problem constants
#define KK   27
#define RR   50000
#define CIN  64
#define COUT 64
#define NIN  150000
#define NOUT 150000

#define TILE    128
#define NTILES  ((RR + TILE - 1) / TILE)      // 391
#define TPB     14                            // tiles per block
#define TPG     7                             // tiles per group (2 groups)
#define NBX     ((NTILES + TPB - 1) / TPB)    // 28
#define THREADS 512

// SMEM: W(hi|lo) 16K, then per-group 3 stages x 32K (stage = AH 16K | AL 16K)
#define OFF_WH  0u
#define OFF_WL  8192u
#define OFF_A   16384u
#define GRP_B   98304u      // 3 * 32768
#define STG_SZ  32768u
#define SMEM_BYTES (16384u + 2u * GRP_B)      // 212992

// ---- global scratch ----------------------------------------------------------
__device__ __align__(16) unsigned short g_xsplit[(size_t)NIN * 128];   // [hi64|lo64]
__device__ __align__(16) unsigned short g_wsplit[(size_t)KK * 8192];   // wh|wl swizzled

// ---- helpers -------------------------------------------------------------------
__device__ __forceinline__ uint32_t smem_u32(const void* p) {
    uint32_t a;
    asm("{ .reg .u64 t; cvta.to.shared.u64 t, %1; cvt.u32.u64 %0, t; }" : "=r"(a) : "l"(p));
    return a;
}
__device__ __forceinline__ void ldm4(uint32_t addr, uint32_t& r0, uint32_t& r1,
                                     uint32_t& r2, uint32_t& r3) {
    asm volatile("ldmatrix.sync.aligned.m8n8.x4.shared.b16 {%0,%1,%2,%3}, [%4];"
                 : "=r"(r0), "=r"(r1), "=r"(r2), "=r"(r3) : "r"(addr));
}
__device__ __forceinline__ void mma_bf16(float4& d,
                                         uint32_t a0, uint32_t a1, uint32_t a2, uint32_t a3,
                                         uint32_t b0, uint32_t b1) {
    asm volatile("mma.sync.aligned.m16n8k16.row.col.f32.bf16.bf16.f32 "
                 "{%0,%1,%2,%3}, {%4,%5,%6,%7}, {%8,%9}, {%0,%1,%2,%3};"
                 : "+f"(d.x), "+f"(d.y), "+f"(d.z), "+f"(d.w)
                 : "r"(a0), "r"(a1), "r"(a2), "r"(a3), "r"(b0), "r"(b1));
}
__device__ __forceinline__ void red4(float* p, float a, float b, float c, float d) {
    asm volatile("red.global.add.v4.f32 [%0], {%1, %2, %3, %4};"
                 :: "l"(p), "f"(a), "f"(b), "f"(c), "f"(d) : "memory");
}
__device__ __forceinline__ void bar_grp(int id) {
    asm volatile("bar.sync %0, 256;" :: "r"(id) : "memory");
}
__device__ __forceinline__ void split_bf16(float v, unsigned short& h, unsigned short& l) {
    __nv_bfloat16 bh = __float2bfloat16(v);
    float fh = __bfloat162float(bh);
    __nv_bfloat16 bl = __float2bfloat16(v - fh);
    h = *reinterpret_cast<unsigned short*>(&bh);
    l = *reinterpret_cast<unsigned short*>(&bl);
}

// ---- fused precompute: split x, split+permute+swizzle W, out = bias -------------
__global__ void precompute_kernel(const float* __restrict__ x,
                                  const float* __restrict__ w,
                                  const float4* __restrict__ bias4,
                                  float4* __restrict__ out4)
{
    int t = blockIdx.x * blockDim.x + threadIdx.x;

    if (t < NIN * 8) {              // split x: 8 floats per thread
        int row = t >> 3, c8 = t & 7;
        const float4* p = (const float4*)(x + (size_t)row * 64 + c8 * 8);
        float4 a = p[0], b = p[1];
        float v[8] = {a.x, a.y, a.z, a.w, b.x, b.y, b.z, b.w};
        unsigned short hi[8], lo[8];
        #pragma unroll
        for (int j = 0; j < 8; j++) split_bf16(v[j], hi[j], lo[j]);
        *(uint4*)(g_xsplit + (size_t)row * 128 + c8 * 8)      = *(uint4*)hi;
        *(uint4*)(g_xsplit + (size_t)row * 128 + 64 + c8 * 8) = *(uint4*)lo;
    }

    if (t < KK * CIN * COUT) {      // split W; perm r gives consecutive-cout d-frags
        int k = t / 4096, rem = t - k * 4096;
        int c = rem >> 6, o = rem & 63;
        unsigned short h, l;
        split_bf16(w[t], h, l);
        int r = ((o >> 1) & 7) * 8 + 2 * (o >> 4) + (o & 1);
        uint32_t off = (uint32_t)r * 128 + (uint32_t)c * 2;
        uint32_t sw  = off ^ ((off >> 3) & 0x70);
        g_wsplit[(size_t)k * 8192 + (sw >> 1)]        = h;
        g_wsplit[(size_t)k * 8192 + 4096 + (sw >> 1)] = l;
    }

    if (t < NOUT * (COUT / 4)) {    // out = bias broadcast
        out4[t] = bias4[t & (COUT / 4 - 1)];
    }
}

// ---- prefetch 8 rule indices for a tile (this thread's gather slots) -------------
__device__ __forceinline__ void idx_prefetch(int t, int k, const int* __restrict__ in_idx,
                                             int gt, int* idxbuf)
{
    const int gi8 = (gt >> 3) & 31;
    #pragma unroll
    for (int it = 0; it < 8; it++) {
        int hid = it * 32 + gi8;
        int rl  = hid >> 1;
        int rg  = t * TILE + rl;
        idxbuf[it] = (rg < RR) ? __ldg(&in_idx[k * RR + rg]) : -1;
    }
}

// ---- async gather of ONE tile using prefetched indices ---------------------------
__device__ __forceinline__ void gather_tile_buf(uint32_t sbase, int g, int sidx,
                                                const int* idxbuf, int gt)
{
    const int gchunk = gt & 7;
    const int gi8    = (gt >> 3) & 31;
    const uint32_t base = sbase + OFF_A + (uint32_t)g * GRP_B + (uint32_t)sidx * STG_SZ;
    #pragma unroll
    for (int it = 0; it < 8; it++) {
        int hid  = it * 32 + gi8;
        int rl   = hid >> 1;
        int half = hid & 1;
        int gi   = idxbuf[it];
        if (gi >= 0) {
            const void* src = (const char*)(g_xsplit + (size_t)gi * 128 + half * 64)
                            + gchunk * 16;
            uint32_t off = (uint32_t)rl * 128 + gchunk * 16;
            uint32_t sw  = off ^ ((off >> 3) & 0x70);
            uint32_t dst = base + (uint32_t)half * 16384u + sw;
            asm volatile("cp.async.cg.shared.global [%0], [%1], 16;"
                         :: "r"(dst), "l"(src) : "memory");
        }
    }
    asm volatile("cp.async.commit_group;" ::: "memory");
}

// ---- main: 2 pipelines, B in regs, idx prefetch, A-frag double buffer ------------
extern "C" __global__ void __launch_bounds__(THREADS, 1)
sparse_mma_kernel(const int* __restrict__ in_idx,
                  const int* __restrict__ out_idx,
                  float*     __restrict__ out)
{
    extern __shared__ __align__(1024) char smem[];
    const uint32_t sbase = smem_u32(smem);
    const int tid  = threadIdx.x;
    const int lane = tid & 31;
    const int wrp  = tid >> 5;          // 0..15
    const int g    = wrp >> 3;          // group 0/1
    const int wg   = wrp & 7;           // warp within group
    const int gt   = tid & 255;         // thread within group
    const int k    = blockIdx.y;
    const int tbase = blockIdx.x * TPB;

    int idxbuf[8];

    // prologue: gathers for first 2 tiles of this group (inline idx), stage W
    idx_prefetch(tbase + g, k, in_idx, gt, idxbuf);
    gather_tile_buf(sbase, g, 0, idxbuf, gt);
    idx_prefetch(tbase + 2 + g, k, in_idx, gt, idxbuf);
    gather_tile_buf(sbase, g, 1, idxbuf, gt);
    // preload indices for tile local-index 2 (issued at loop i=0)
    idx_prefetch(tbase + 4 + g, k, in_idx, gt, idxbuf);
    {
        const uint4* wgp = (const uint4*)(g_wsplit + (size_t)k * 8192);
        uint4*       wsm = (uint4*)(smem + OFF_WH);
        #pragma unroll
        for (int i = tid; i < 1024; i += THREADS) wsm[i] = wgp[i];
    }
    __syncthreads();   // W visible for B-frag ldmatrix

    // warp roles within group: n-half h, rule-slice s8 (32 rules each)
    const int h   = wg & 1;
    const int s8  = wg >> 1;            // 0..3
    const int mrow0 = s8 * 32 + (lane & 15);

    // ---- B fragments: load ONCE into registers ----
    uint32_t Bh[4][8], Bl[4][8];
    {
        const uint32_t b_xor  = (uint32_t)((lane & 7) << 4);
        const uint32_t b_kofs = (uint32_t)(((lane >> 3) & 1) * 16);
        uint32_t b_rb[2];
        #pragma unroll
        for (int pp = 0; pp < 2; pp++) {
            int p = 2 * h + pp;
            b_rb[pp] = (uint32_t)(((2 * p + (lane >> 4)) * 8 + (lane & 7)) * 128);
        }
        #pragma unroll
        for (int ks = 0; ks < 4; ks++) {
            uint32_t colb = (uint32_t)(32 * ks) + b_kofs;
            #pragma unroll
            for (int pp = 0; pp < 2; pp++) {
                ldm4(sbase + OFF_WH + b_rb[pp] + (colb ^ b_xor),
                     Bh[ks][4 * pp], Bh[ks][4 * pp + 1], Bh[ks][4 * pp + 2], Bh[ks][4 * pp + 3]);
                ldm4(sbase + OFF_WL + b_rb[pp] + (colb ^ b_xor),
                     Bl[ks][4 * pp], Bl[ks][4 * pp + 1], Bl[ks][4 * pp + 2], Bl[ks][4 * pp + 3]);
            }
        }
    }

    // A ldmatrix addressing (per mb: +16 rows = +2048B)
    const uint32_t a_xor0 = (uint32_t)((mrow0 & 7) << 4);
    const uint32_t a_rb   = (uint32_t)mrow0 * 128u;
    const uint32_t a_kofs = (uint32_t)(((lane >> 4) & 1) * 16);
    const uint32_t gbase  = sbase + OFF_A + (uint32_t)g * GRP_B;

    // epilogue constants
    const int tq    = lane & 3;
    const int rrow  = 32 * s8 + (lane >> 2);
    const int cbase = 16 * tq + 8 * h;
    const int barid = 1 + g;

    #pragma unroll 1
    for (int i = 0; i < TPG; i++) {
        int t = tbase + 2 * i + g;

        // wait for this tile's gather, group-local visibility barrier
        if (i < TPG - 1) asm volatile("cp.async.wait_group 1;" ::: "memory");
        else             asm volatile("cp.async.wait_group 0;" ::: "memory");
        bar_grp(barid);   // also: group finished reading stage (i-1)%3 last iter

        // issue gather for tile i+2 (indices already in registers)
        if (i + 2 < TPG)
            gather_tile_buf(sbase, g, (i + 2) % 3, idxbuf, gt);

        // prefetch this tile's 4 output indices (hides under MMA below)
        int obuf[4];
        #pragma unroll
        for (int mb = 0; mb < 2; mb++) {
            int rg1 = t * TILE + rrow + 16 * mb;
            int rg2 = rg1 + 8;
            obuf[2 * mb]     = (rg1 < RR) ? __ldg(&out_idx[k * RR + rg1]) : -1;
            obuf[2 * mb + 1] = (rg2 < RR) ? __ldg(&out_idx[k * RR + rg2]) : -1;
        }
        // prefetch rule indices for tile i+3 (used 2 iterations from now)
        if (i + 3 < TPG)
            idx_prefetch(tbase + 2 * (i + 3) + g, k, in_idx, gt, idxbuf);

        // ---- MMA with A-frag double buffer over flat (mb,ks) steps ----
        const uint32_t stage = gbase + (uint32_t)(i % 3) * STG_SZ;
        const uint32_t ab    = stage + a_rb;

        // frag buffers: [0..3]=hi, [4..7]=lo
        uint32_t cur[8], nxt[8];
        {   // load step 0: mb=0, ks=0
            uint32_t cola = a_kofs;
            ldm4(ab + (cola ^ a_xor0), cur[0], cur[1], cur[2], cur[3]);
            ldm4(ab + 16384u + (cola ^ a_xor0), cur[4], cur[5], cur[6], cur[7]);
        }

        #pragma unroll
        for (int mb = 0; mb < 2; mb++) {
            float4 acc[4];
            #pragma unroll
            for (int q = 0; q < 4; q++) acc[q] = make_float4(0.f, 0.f, 0.f, 0.f);

            #pragma unroll
            for (int ks = 0; ks < 4; ks++) {
                // prefetch next step's A frags (next ks, or mb=1 ks=0)
                int step = mb * 4 + ks;
                if (step < 7) {
                    int nmb = (step + 1) >> 2, nks = (step + 1) & 3;
                    uint32_t cola = (uint32_t)(32 * nks) + a_kofs;
                    uint32_t nab  = ab + (uint32_t)nmb * 2048u;
                    ldm4(nab + (cola ^ a_xor0), nxt[0], nxt[1], nxt[2], nxt[3]);
                    ldm4(nab + 16384u + (cola ^ a_xor0), nxt[4], nxt[5], nxt[6], nxt[7]);
                }
                // 12 HMMA on cur
                #pragma unroll
                for (int q = 0; q < 4; q++)
                    mma_bf16(acc[q], cur[0], cur[1], cur[2], cur[3],
                             Bh[ks][2 * q], Bh[ks][2 * q + 1]);
                #pragma unroll
                for (int q = 0; q < 4; q++)
                    mma_bf16(acc[q], cur[4], cur[5], cur[6], cur[7],
                             Bh[ks][2 * q], Bh[ks][2 * q + 1]);
                #pragma unroll
                for (int q = 0; q < 4; q++)
                    mma_bf16(acc[q], cur[0], cur[1], cur[2], cur[3],
                             Bl[ks][2 * q], Bl[ks][2 * q + 1]);
                // rotate buffers
                if (step < 7) {
                    #pragma unroll
                    for (int j = 0; j < 8; j++) cur[j] = nxt[j];
                }
            }

            int o1 = obuf[2 * mb], o2 = obuf[2 * mb + 1];
            if (o1 >= 0) {
                float* b = out + (size_t)o1 * COUT + cbase;
                red4(b,     acc[0].x, acc[0].y, acc[1].x, acc[1].y);
                red4(b + 4, acc[2].x, acc[2].y, acc[3].x, acc[3].y);
            }
            if (o2 >= 0) {
                float* b = out + (size_t)o2 * COUT + cbase;
                red4(b,     acc[0].z, acc[0].w, acc[1].z, acc[1].w);
                red4(b + 4, acc[2].z, acc[2].w, acc[3].z, acc[3].w);
            }
        }
    }
}

extern "C" void kernel_launch(void* const* d_in, const int* in_sizes, int n_in,
                              void* d_out, int out_size)
{
    const float* x       = (const float*)d_in[0];
    const float* w       = (const float*)d_in[1];
    const float* bias    = (const float*)d_in[2];
    const int*   in_idx  = (const int*)d_in[3];
    const int*   out_idx = (const int*)d_in[4];
    float*       out     = (float*)d_out;

    {   // fused: split x, split W, out = bias
        int nmax = NOUT * (COUT / 4);   // largest range (2.4M)
        precompute_kernel<<<(nmax + 255) / 256, 256>>>(x, w, (const float4*)bias,
                                                       (float4*)out);
    }

    cudaFuncSetAttribute(sparse_mma_kernel,
                         cudaFuncAttributeMaxDynamicSharedMemorySize, SMEM_BYTES);
    dim3 grid(NBX, KK);
    sparse_mma_kernel<<<grid, THREADS, SMEM_BYTES>>>(in_idx, out_idx, out);
}